// round 12
// baseline (speedup 1.0000x reference)
#include <cuda_runtime.h>
#include <cuda_fp16.h>
#include <cstdint>
#include <float.h>

#define NPIX 65536
#define FDIM 224
#define PDIM 6
#define HDIM 256
#define NCHUNK 512          // pixel row-blocks (128 px each)

// ------------------------- static device scratch ---------------------------
__device__ __half g_Yh[NPIX * FDIM];
__device__ __half g_Yl[NPIX * FDIM];
__device__ __half g_h1h[NPIX * HDIM];
__device__ __half g_h1l[NPIX * HDIM];
__device__ __half g_h2h[NPIX * HDIM];
__device__ __half g_h2l[NPIX * HDIM];
__device__ int    g_cls[NPIX];
__device__ float  g_M[PDIM * FDIM];
__device__ __half g_W1Th[HDIM * FDIM];
__device__ __half g_W1Tl[HDIM * FDIM];
__device__ __half g_W2Th[HDIM * HDIM];
__device__ __half g_W2Tl[HDIM * HDIM];
__device__ __half g_W3Th[FDIM * HDIM];
__device__ __half g_W3Tl[FDIM * HDIM];
// per-rowblock partials: [rowblk][class][{m,s,sy}][FDIM]
__device__ float  g_part[NCHUNK * PDIM * 3 * FDIM];

// ------------------------------ PTX helpers --------------------------------
__device__ __forceinline__ uint32_t smem_u32(const void* p) {
    uint32_t a;
    asm("{ .reg .u64 t; cvta.to.shared.u64 t, %1; cvt.u32.u64 %0, t; }"
        : "=r"(a) : "l"(p));
    return a;
}
__device__ __forceinline__ void cpa16(uint32_t dst, const void* src, uint32_t sz) {
    asm volatile("cp.async.cg.shared.global [%0], [%1], 16, %2;"
                 :: "r"(dst), "l"(src), "r"(sz) : "memory");
}
__device__ __forceinline__ void cpa_commit() {
    asm volatile("cp.async.commit_group;" ::: "memory");
}
template <int n> __device__ __forceinline__ void cpa_wait() {
    asm volatile("cp.async.wait_group %0;" :: "n"(n) : "memory");
}
__device__ __forceinline__ void ldsm4(uint32_t* r, uint32_t addr) {
    asm volatile("ldmatrix.sync.aligned.m8n8.x4.shared.b16 {%0,%1,%2,%3}, [%4];"
                 : "=r"(r[0]), "=r"(r[1]), "=r"(r[2]), "=r"(r[3]) : "r"(addr));
}
__device__ __forceinline__ void mma_f16(float* d, const uint32_t* a, const uint32_t* b) {
    asm volatile(
        "mma.sync.aligned.m16n8k16.row.col.f32.f16.f16.f32 "
        "{%0,%1,%2,%3}, {%4,%5,%6,%7}, {%8,%9}, {%0,%1,%2,%3};"
        : "+f"(d[0]), "+f"(d[1]), "+f"(d[2]), "+f"(d[3])
        : "r"(a[0]), "r"(a[1]), "r"(a[2]), "r"(a[3]), "r"(b[0]), "r"(b[1]));
}
__device__ __forceinline__ void split_h(float v, __half& hi, __half& lo) {
    hi = __float2half_rn(v);
    lo = __float2half_rn(v - __half2float(hi));
}

// ---------------------------------------------------------------------------
// fp16x3 mma.sync GEMM: C = act(A @ BT^T + bias), fp32-accurate.
// Block 128x128, 8 warps (2x4), warp tile 64x32, K chunks of 32, 2-stage
// cp.async, one __syncthreads per chunk.
// SPLIT_OUT: hi/lo fp16 pair outputs (chained layers).
// REDUCE (GEMM3): skip storing C; accumulate per-class plain-exp sums
//   (s = sum e^l, sy = sum e^l*y) per feature via smem atomics, straight
//   from accumulator registers. Partials written with m=0 (combine kernel
//   merges them exactly). No logits array, no separate reduction kernel.
// ---------------------------------------------------------------------------
template <int N, int K, bool RELU, bool SPLIT_OUT, bool REDUCE>
__global__ __launch_bounds__(256, 2) void mma_gemm_f16(
    const __half* __restrict__ Ah, const __half* __restrict__ Al,
    const __half* __restrict__ Bh, const __half* __restrict__ Bl,
    const float* __restrict__ bias,
    float* __restrict__ Cf, __half* __restrict__ Ch, __half* __restrict__ Cl,
    const float* __restrict__ Yfull, const int* __restrict__ clsg,
    float* __restrict__ part)
{
    constexpr int NC = K / 32;
    constexpr int ROWB = 80;               // bytes/row: 64B data + 16B pad
    constexpr int COMPB = 128 * ROWB;      // 10240 per component tile
    constexpr int STAGEB = 4 * COMPB;      // 40960: [Ah][Al][Bh][Bl]
    constexpr int STATS_OFF = 2 * STAGEB;  // 81920: 128 cols x 6 x 2 floats
    constexpr int CLS_OFF = STATS_OFF + 128 * PDIM * 2 * 4;  // 88064

    extern __shared__ char sh[];
    const uint32_t sb = smem_u32(sh);

    const int t = threadIdx.x;
    const int lane = t & 31, wid = t >> 5;
    const int wr = wid >> 2;               // 0..1
    const int wc = wid & 3;                // 0..3
    const int row0 = blockIdx.y * 128;
    const int col0 = blockIdx.x * 128;

    if (REDUCE) {
        float* stats = (float*)(sh + STATS_OFF);
        for (int i = t; i < 128 * PDIM * 2; i += 256) stats[i] = 0.f;
        int* scls = (int*)(sh + CLS_OFF);
        if (t < 128) scls[t] = clsg[row0 + t];
        // visibility guaranteed by the mainloop's per-chunk barriers
    }

    float acc[4][4][4];
#pragma unroll
    for (int i = 0; i < 4; i++)
#pragma unroll
        for (int j = 0; j < 4; j++)
#pragma unroll
            for (int k = 0; k < 4; k++) acc[i][j][k] = 0.0f;

    const int cr = t >> 2;
    const int g  = t & 3;
    const uint32_t dOff1 = (uint32_t)(cr * ROWB + g * 16);
    const uint32_t dOff2 = dOff1 + (uint32_t)(64 * ROWB);

    const __half* Ah0 = Ah + (long)(row0 + cr) * K + g * 8;
    const __half* Al0 = Al + (long)(row0 + cr) * K + g * 8;
    int bn1 = col0 + cr, bn2 = col0 + cr + 64;
    const uint32_t bs1 = (bn1 < N) ? 16u : 0u;
    const uint32_t bs2 = (bn2 < N) ? 16u : 0u;
    if (bn1 >= N) bn1 = N - 1;
    if (bn2 >= N) bn2 = N - 1;
    const __half* Bh1 = Bh + (long)bn1 * K + g * 8;
    const __half* Bh2 = Bh + (long)bn2 * K + g * 8;
    const __half* Bl1 = Bl + (long)bn1 * K + g * 8;
    const __half* Bl2 = Bl + (long)bn2 * K + g * 8;

    const uint32_t aLm = (uint32_t)((wr * 64 + (lane & 15)) * ROWB + (lane >> 4) * 16);
    const uint32_t bLm = (uint32_t)((wc * 32 + (lane & 7) + ((lane >> 4) << 3)) * ROWB
                                    + ((lane >> 3) & 1) * 16);

    auto load_chunk = [&](int stage, int k0) {
        const uint32_t st = sb + (uint32_t)(stage * STAGEB);
        cpa16(st + dOff1,                 Ah0 + k0,           16u);
        cpa16(st + dOff2,                 Ah0 + k0 + 64L * K, 16u);
        cpa16(st + COMPB + dOff1,         Al0 + k0,           16u);
        cpa16(st + COMPB + dOff2,         Al0 + k0 + 64L * K, 16u);
        cpa16(st + 2 * COMPB + dOff1,     Bh1 + k0,           bs1);
        cpa16(st + 2 * COMPB + dOff2,     Bh2 + k0,           bs2);
        cpa16(st + 3 * COMPB + dOff1,     Bl1 + k0,           bs1);
        cpa16(st + 3 * COMPB + dOff2,     Bl2 + k0,           bs2);
        cpa_commit();
    };

    load_chunk(0, 0);

    for (int c = 0; c < NC; c++) {
        const int buf = c & 1;
        cpa_wait<0>();
        __syncthreads();
        if (c + 1 < NC) load_chunk(buf ^ 1, (c + 1) * 32);

        const uint32_t st = sb + (uint32_t)(buf * STAGEB);
        const uint32_t aHB = st + aLm;
        const uint32_t aLB = st + COMPB + aLm;
        const uint32_t bHB = st + 2 * COMPB + bLm;
        const uint32_t bLB = st + 3 * COMPB + bLm;

#pragma unroll
        for (int kk = 0; kk < 2; kk++) {
            uint32_t bh[4][2], bl[4][2];
#pragma unroll
            for (int pr = 0; pr < 2; pr++) {
                const uint32_t o = (uint32_t)(pr * 16 * ROWB + kk * 32);
                uint32_t r4[4];
                ldsm4(r4, bHB + o);
                bh[pr * 2][0] = r4[0]; bh[pr * 2][1] = r4[1];
                bh[pr * 2 + 1][0] = r4[2]; bh[pr * 2 + 1][1] = r4[3];
                ldsm4(r4, bLB + o);
                bl[pr * 2][0] = r4[0]; bl[pr * 2][1] = r4[1];
                bl[pr * 2 + 1][0] = r4[2]; bl[pr * 2 + 1][1] = r4[3];
            }
#pragma unroll
            for (int mp = 0; mp < 2; mp++) {
                const int m0 = mp * 2, m1 = mp * 2 + 1;
                const uint32_t o0 = (uint32_t)(m0 * 16 * ROWB + kk * 32);
                const uint32_t o1 = (uint32_t)(m1 * 16 * ROWB + kk * 32);
                uint32_t ah0[4], al0[4], ah1[4], al1[4];
                ldsm4(ah0, aHB + o0);
                ldsm4(al0, aLB + o0);
                ldsm4(ah1, aHB + o1);
                ldsm4(al1, aLB + o1);
#pragma unroll
                for (int nt = 0; nt < 4; nt++) mma_f16(acc[m0][nt], ah0, bh[nt]);
#pragma unroll
                for (int nt = 0; nt < 4; nt++) mma_f16(acc[m1][nt], ah1, bh[nt]);
#pragma unroll
                for (int nt = 0; nt < 4; nt++) mma_f16(acc[m0][nt], al0, bh[nt]);
#pragma unroll
                for (int nt = 0; nt < 4; nt++) mma_f16(acc[m1][nt], al1, bh[nt]);
#pragma unroll
                for (int nt = 0; nt < 4; nt++) mma_f16(acc[m0][nt], ah0, bl[nt]);
#pragma unroll
                for (int nt = 0; nt < 4; nt++) mma_f16(acc[m1][nt], ah1, bl[nt]);
            }
        }
    }

    const int rbase = wr * 64 + (lane >> 2);          // local row
    const int cbase = wc * 32 + (lane & 3) * 2;       // local col

    if (REDUCE) {
        // ---- fused plain-exp class-masked reduction (no staging, no chain) ----
        float* stats = (float*)(sh + STATS_OFF);
        const int* scls = (const int*)(sh + CLS_OFF);
#pragma unroll
        for (int nt = 0; nt < 4; nt++) {
            const int cc = cbase + nt * 8;
            const int gf = col0 + cc;
            if (gf < N) {
                const float bx = bias[gf], by = bias[gf + 1];
#pragma unroll
                for (int mt = 0; mt < 4; mt++) {
#pragma unroll
                    for (int qr = 0; qr < 2; qr++) {
                        const int r = rbase + mt * 16 + qr * 8;
                        const int c2 = scls[r];
                        float2 yv = *(const float2*)&Yfull[(long)(row0 + r) * FDIM + gf];
                        float e0 = __expf(acc[mt][nt][qr * 2]     + bx);
                        float e1 = __expf(acc[mt][nt][qr * 2 + 1] + by);
                        atomicAdd(&stats[(cc * PDIM + c2) * 2],           e0);
                        atomicAdd(&stats[(cc * PDIM + c2) * 2 + 1],       e0 * yv.x);
                        atomicAdd(&stats[((cc + 1) * PDIM + c2) * 2],     e1);
                        atomicAdd(&stats[((cc + 1) * PDIM + c2) * 2 + 1], e1 * yv.y);
                    }
                }
            }
        }
        __syncthreads();
        if (t < 128) {
            const int gf = col0 + t;
            if (gf < N) {
#pragma unroll
                for (int p = 0; p < PDIM; p++) {
                    long base = (((long)blockIdx.y * PDIM + p) * 3) * FDIM + gf;
                    part[base]            = 0.f;   // m = 0 (plain sums)
                    part[base + FDIM]     = stats[(t * PDIM + p) * 2];
                    part[base + 2 * FDIM] = stats[(t * PDIM + p) * 2 + 1];
                }
            }
        }
        return;
    }

    // ---- standard epilogue ----
    const int grb = row0 + rbase;
    const int gcb = col0 + cbase;
#pragma unroll
    for (int nt = 0; nt < 4; nt++) {
        const int cc = gcb + nt * 8;
        if (cc < N) {
            const float bx = bias[cc], by = bias[cc + 1];
#pragma unroll
            for (int mt = 0; mt < 4; mt++) {
                const int r = grb + mt * 16;
                float v[4];
                v[0] = acc[mt][nt][0] + bx; v[1] = acc[mt][nt][1] + by;
                v[2] = acc[mt][nt][2] + bx; v[3] = acc[mt][nt][3] + by;
                if (RELU) {
#pragma unroll
                    for (int q = 0; q < 4; q++) v[q] = fmaxf(v[q], 0.f);
                }
                if (SPLIT_OUT) {
                    __half h0, l0, h1x, l1, h2x, l2, h3, l3;
                    split_h(v[0], h0, l0); split_h(v[1], h1x, l1);
                    split_h(v[2], h2x, l2); split_h(v[3], h3, l3);
                    *(__half2*)&Ch[(long)r * N + cc]       = __halves2half2(h0, h1x);
                    *(__half2*)&Cl[(long)r * N + cc]       = __halves2half2(l0, l1);
                    *(__half2*)&Ch[(long)(r + 8) * N + cc] = __halves2half2(h2x, h3);
                    *(__half2*)&Cl[(long)(r + 8) * N + cc] = __halves2half2(l2, l3);
                } else {
                    *(float2*)&Cf[(long)r * N + cc]       = make_float2(v[0], v[1]);
                    *(float2*)&Cf[(long)(r + 8) * N + cc] = make_float2(v[2], v[3]);
                }
            }
        }
    }
}

// ---------------------------------------------------------------------------
__global__ __launch_bounds__(256) void split_kernel(
    const float* __restrict__ in, __half* __restrict__ hi, __half* __restrict__ lo,
    int n4)
{
    int i = blockIdx.x * 256 + threadIdx.x;
    if (i >= n4) return;
    float4 v = ((const float4*)in)[i];
    __half h0, l0, h1, l1, h2, l2, h3, l3;
    split_h(v.x, h0, l0); split_h(v.y, h1, l1);
    split_h(v.z, h2, l2); split_h(v.w, h3, l3);
    ((__half2*)hi)[i * 2]     = __halves2half2(h0, h1);
    ((__half2*)hi)[i * 2 + 1] = __halves2half2(h2, h3);
    ((__half2*)lo)[i * 2]     = __halves2half2(l0, l1);
    ((__half2*)lo)[i * 2 + 1] = __halves2half2(l2, l3);
}

// ---------------------------------------------------------------------------
__global__ void transpose_split_all(
    const float* __restrict__ W1, __half* __restrict__ T1h, __half* __restrict__ T1l,
    const float* __restrict__ W2, __half* __restrict__ T2h, __half* __restrict__ T2l,
    const float* __restrict__ W3, __half* __restrict__ T3h, __half* __restrict__ T3l)
{
    const float* W; __half* Th; __half* Tl; int R, C;
    if (blockIdx.z == 0)      { W = W1; Th = T1h; Tl = T1l; R = FDIM; C = HDIM; }
    else if (blockIdx.z == 1) { W = W2; Th = T2h; Tl = T2l; R = HDIM; C = HDIM; }
    else                      { W = W3; Th = T3h; Tl = T3l; R = HDIM; C = FDIM; }
    if ((int)blockIdx.x * 32 >= C || (int)blockIdx.y * 32 >= R) return;

    __shared__ float tb[32][33];
    int c = blockIdx.x * 32 + threadIdx.x;
    int r0 = blockIdx.y * 32;
    for (int j = threadIdx.y; j < 32; j += 8)
        tb[j][threadIdx.x] = W[(r0 + j) * C + c];
    __syncthreads();
    int rOut = r0 + threadIdx.x;
    int cBase = blockIdx.x * 32;
    for (int j = threadIdx.y; j < 32; j += 8) {
        float v = tb[threadIdx.x][j];
        __half h, l;
        split_h(v, h, l);
        Th[(long)(cBase + j) * R + rOut] = h;
        Tl[(long)(cBase + j) * R + rOut] = l;
    }
}

// ---------------------------------------------------------------------------
__global__ __launch_bounds__(256) void cls_kernel2(
    const float* __restrict__ ab, int* __restrict__ cls)
{
    int i = blockIdx.x * 256 + threadIdx.x;   // pair index
    if (i >= NPIX / 2) return;
    const float4* p = (const float4*)(ab + (long)i * 12);
    float4 v0 = p[0], v1 = p[1], v2 = p[2];
    float a[6] = { v0.x, v0.y, v0.z, v0.w, v1.x, v1.y };
    float b[6] = { v1.z, v1.w, v2.x, v2.y, v2.z, v2.w };
    int ba = 0, bb = 0;
    float ma = a[0], mb = b[0];
#pragma unroll
    for (int q = 1; q < 6; q++) {
        if (a[q] > ma) { ma = a[q]; ba = q; }
        if (b[q] > mb) { mb = b[q]; bb = q; }
    }
    cls[i * 2] = ba;
    cls[i * 2 + 1] = bb;
}

// ---------------------------------------------------------------------------
// grid PDIM blocks x 224 threads: merge per-rowblock partials
__global__ __launch_bounds__(224) void endmember_combine2(float* __restrict__ Mo) {
    const int p = blockIdx.x;
    const int f = threadIdx.x;
    float m = -FLT_MAX, s = 0.f, sy = 0.f;
    for (int b = 0; b < NCHUNK; b++) {
        long base = (((long)b * PDIM + p) * 3) * FDIM + f;
        float m2 = g_part[base];
        float s2 = g_part[base + FDIM];
        float sy2 = g_part[base + 2 * FDIM];
        float mx = fmaxf(m, m2);
        float e1 = __expf(m - mx), e2 = __expf(m2 - mx);
        s  = s * e1 + s2 * e2;
        sy = sy * e1 + sy2 * e2;
        m = mx;
    }
    Mo[p * FDIM + f] = (s > 0.f) ? (sy / s) : 0.0f;
}

// ---------------------------------------------------------------------------
__global__ __launch_bounds__(224) void yhat_kernel2(
    const float* __restrict__ ab, const float* __restrict__ M,
    float* __restrict__ out)
{
    constexpr int CH = NPIX / NCHUNK;  // 128
    __shared__ float sM[PDIM * FDIM];
    __shared__ float sab[CH * PDIM];
    const int t = threadIdx.x;
    const int n0 = blockIdx.x * CH;
    for (int i = t; i < PDIM * FDIM; i += 224) sM[i] = M[i];
    for (int i = t; i < CH * PDIM; i += 224) sab[i] = ab[(long)n0 * PDIM + i];
    __syncthreads();

    for (int i = 0; i < CH; i++) {
        float acc = 0.f;
#pragma unroll
        for (int p = 0; p < PDIM; p++) acc += sab[i * PDIM + p] * sM[p * FDIM + t];
        out[(long)(n0 + i) * FDIM + t] = acc;
    }
}

// ---------------------------------------------------------------------------
extern "C" void kernel_launch(void* const* d_in, const int* in_sizes, int n_in,
                              void* d_out, int out_size)
{
    const float* ab = (const float*)d_in[0];
    const float* Y  = (const float*)d_in[1];
    const float* W1 = (const float*)d_in[2];
    const float* b1 = (const float*)d_in[3];
    const float* W2 = (const float*)d_in[4];
    const float* b2 = (const float*)d_in[5];
    const float* W3 = (const float*)d_in[6];
    const float* b3 = (const float*)d_in[7];
    float* out = (float*)d_out;

    __half *yh, *yl, *h1h, *h1l, *h2h, *h2l;
    __half *w1h, *w1l, *w2h, *w2l, *w3h, *w3l;
    float *M, *part;
    int* cls;
    cudaGetSymbolAddress((void**)&yh,  g_Yh);
    cudaGetSymbolAddress((void**)&yl,  g_Yl);
    cudaGetSymbolAddress((void**)&h1h, g_h1h);
    cudaGetSymbolAddress((void**)&h1l, g_h1l);
    cudaGetSymbolAddress((void**)&h2h, g_h2h);
    cudaGetSymbolAddress((void**)&h2l, g_h2l);
    cudaGetSymbolAddress((void**)&w1h, g_W1Th);
    cudaGetSymbolAddress((void**)&w1l, g_W1Tl);
    cudaGetSymbolAddress((void**)&w2h, g_W2Th);
    cudaGetSymbolAddress((void**)&w2l, g_W2Tl);
    cudaGetSymbolAddress((void**)&w3h, g_W3Th);
    cudaGetSymbolAddress((void**)&w3l, g_W3Tl);
    cudaGetSymbolAddress((void**)&cls, g_cls);
    cudaGetSymbolAddress((void**)&M,   g_M);
    cudaGetSymbolAddress((void**)&part, g_part);

    constexpr int SMEM = 2 * 4 * 128 * 80;           // 81920 (GEMM1/2)
    constexpr int SMEM_RED = SMEM + 128 * PDIM * 2 * 4 + 128 * 4;  // 88576 (GEMM3)
    cudaFuncSetAttribute(mma_gemm_f16<HDIM, FDIM, true, true, false>,
                         cudaFuncAttributeMaxDynamicSharedMemorySize, SMEM);
    cudaFuncSetAttribute(mma_gemm_f16<HDIM, HDIM, true, true, false>,
                         cudaFuncAttributeMaxDynamicSharedMemorySize, SMEM);
    cudaFuncSetAttribute(mma_gemm_f16<FDIM, HDIM, false, false, true>,
                         cudaFuncAttributeMaxDynamicSharedMemorySize, SMEM_RED);

    // prep
    split_kernel<<<(NPIX * FDIM / 4 + 255) / 256, 256>>>(Y, yh, yl, NPIX * FDIM / 4);
    transpose_split_all<<<dim3(8, 8, 3), dim3(32, 8)>>>(
        W1, w1h, w1l, W2, w2h, w2l, W3, w3h, w3l);
    cls_kernel2<<<(NPIX / 2 + 255) / 256, 256>>>(ab, cls);

    // GEMM chain; GEMM3 fuses the per-class masked reduction (plain-exp sums)
    mma_gemm_f16<HDIM, FDIM, true, true, false><<<dim3(2, NPIX / 128), 256, SMEM>>>(
        yh, yl, w1h, w1l, b1, nullptr, h1h, h1l, nullptr, nullptr, nullptr);
    mma_gemm_f16<HDIM, HDIM, true, true, false><<<dim3(2, NPIX / 128), 256, SMEM>>>(
        h1h, h1l, w2h, w2l, b2, nullptr, h2h, h2l, nullptr, nullptr, nullptr);
    mma_gemm_f16<FDIM, HDIM, false, false, true><<<dim3(2, NPIX / 128), 256, SMEM_RED>>>(
        h2h, h2l, w3h, w3l, b3, nullptr, nullptr, nullptr, Y, cls, part);

    // merge partials -> endmembers
    endmember_combine2<<<PDIM, 224>>>(M);

    // reconstruction
    yhat_kernel2<<<NCHUNK, 224>>>(ab, M, out);
}

// round 13
// speedup vs baseline: 1.1178x; 1.1178x over previous
#include <cuda_runtime.h>
#include <cuda_fp16.h>
#include <cstdint>
#include <float.h>

#define NPIX 65536
#define FDIM 224
#define PDIM 6
#define HDIM 256
#define NCHUNK 512          // pixel row-blocks (128 px each)

// ------------------------- static device scratch ---------------------------
__device__ __half g_Yh[NPIX * FDIM];
__device__ __half g_Yl[NPIX * FDIM];
__device__ __half g_h1h[NPIX * HDIM];
__device__ __half g_h1l[NPIX * HDIM];
__device__ __half g_h2h[NPIX * HDIM];
__device__ __half g_h2l[NPIX * HDIM];
__device__ __half g_logits[NPIX * FDIM];   // fp16 logits (hi)
__device__ int    g_cls[NPIX];
__device__ float  g_M[PDIM * FDIM];
__device__ __half g_W1Th[HDIM * FDIM];
__device__ __half g_W1Tl[HDIM * FDIM];
__device__ __half g_W2Th[HDIM * HDIM];
__device__ __half g_W2Tl[HDIM * HDIM];
__device__ __half g_W3Th[FDIM * HDIM];
__device__ __half g_W3Tl[FDIM * HDIM];
// per-rowblock partials: [rowblk][class][{m,s,sy}][FDIM]
__device__ float  g_part[NCHUNK * PDIM * 3 * FDIM];

// ------------------------------ PTX helpers --------------------------------
__device__ __forceinline__ uint32_t smem_u32(const void* p) {
    uint32_t a;
    asm("{ .reg .u64 t; cvta.to.shared.u64 t, %1; cvt.u32.u64 %0, t; }"
        : "=r"(a) : "l"(p));
    return a;
}
__device__ __forceinline__ void cpa16(uint32_t dst, const void* src, uint32_t sz) {
    asm volatile("cp.async.cg.shared.global [%0], [%1], 16, %2;"
                 :: "r"(dst), "l"(src), "r"(sz) : "memory");
}
__device__ __forceinline__ void cpa_commit() {
    asm volatile("cp.async.commit_group;" ::: "memory");
}
template <int n> __device__ __forceinline__ void cpa_wait() {
    asm volatile("cp.async.wait_group %0;" :: "n"(n) : "memory");
}
__device__ __forceinline__ void ldsm4(uint32_t* r, uint32_t addr) {
    asm volatile("ldmatrix.sync.aligned.m8n8.x4.shared.b16 {%0,%1,%2,%3}, [%4];"
                 : "=r"(r[0]), "=r"(r[1]), "=r"(r[2]), "=r"(r[3]) : "r"(addr));
}
__device__ __forceinline__ void mma_f16(float* d, const uint32_t* a, const uint32_t* b) {
    asm volatile(
        "mma.sync.aligned.m16n8k16.row.col.f32.f16.f16.f32 "
        "{%0,%1,%2,%3}, {%4,%5,%6,%7}, {%8,%9}, {%0,%1,%2,%3};"
        : "+f"(d[0]), "+f"(d[1]), "+f"(d[2]), "+f"(d[3])
        : "r"(a[0]), "r"(a[1]), "r"(a[2]), "r"(a[3]), "r"(b[0]), "r"(b[1]));
}
__device__ __forceinline__ void split_h(float v, __half& hi, __half& lo) {
    hi = __float2half_rn(v);
    lo = __float2half_rn(v - __half2float(hi));
}

// ---------------------------------------------------------------------------
// fp16x3 mma.sync GEMM: C = act(A @ BT^T + bias), fp32-accurate.
// Block 128x128, 8 warps (2x4), warp tile 64x32, K chunks of 32, 2-stage
// cp.async, one __syncthreads per chunk, paired-mt MMA schedule (R10 champion).
// SPLIT_OUT: hi/lo fp16 pair outputs (chained layers).
// HALF_OUT: single fp16 output (logits).
// ---------------------------------------------------------------------------
template <int N, int K, bool RELU, bool SPLIT_OUT, bool HALF_OUT>
__global__ __launch_bounds__(256, 2) void mma_gemm_f16(
    const __half* __restrict__ Ah, const __half* __restrict__ Al,
    const __half* __restrict__ Bh, const __half* __restrict__ Bl,
    const float* __restrict__ bias,
    float* __restrict__ Cf, __half* __restrict__ Ch, __half* __restrict__ Cl)
{
    constexpr int NC = K / 32;
    constexpr int ROWB = 80;               // bytes/row: 64B data + 16B pad
    constexpr int COMPB = 128 * ROWB;      // 10240 per component tile
    constexpr int STAGEB = 4 * COMPB;      // 40960: [Ah][Al][Bh][Bl]

    extern __shared__ char sh[];
    const uint32_t sb = smem_u32(sh);

    const int t = threadIdx.x;
    const int lane = t & 31, wid = t >> 5;
    const int wr = wid >> 2;               // 0..1
    const int wc = wid & 3;                // 0..3
    const int row0 = blockIdx.y * 128;
    const int col0 = blockIdx.x * 128;

    float acc[4][4][4];
#pragma unroll
    for (int i = 0; i < 4; i++)
#pragma unroll
        for (int j = 0; j < 4; j++)
#pragma unroll
            for (int k = 0; k < 4; k++) acc[i][j][k] = 0.0f;

    const int cr = t >> 2;
    const int g  = t & 3;
    const uint32_t dOff1 = (uint32_t)(cr * ROWB + g * 16);
    const uint32_t dOff2 = dOff1 + (uint32_t)(64 * ROWB);

    const __half* Ah0 = Ah + (long)(row0 + cr) * K + g * 8;
    const __half* Al0 = Al + (long)(row0 + cr) * K + g * 8;
    int bn1 = col0 + cr, bn2 = col0 + cr + 64;
    const uint32_t bs1 = (bn1 < N) ? 16u : 0u;
    const uint32_t bs2 = (bn2 < N) ? 16u : 0u;
    if (bn1 >= N) bn1 = N - 1;
    if (bn2 >= N) bn2 = N - 1;
    const __half* Bh1 = Bh + (long)bn1 * K + g * 8;
    const __half* Bh2 = Bh + (long)bn2 * K + g * 8;
    const __half* Bl1 = Bl + (long)bn1 * K + g * 8;
    const __half* Bl2 = Bl + (long)bn2 * K + g * 8;

    const uint32_t aLm = (uint32_t)((wr * 64 + (lane & 15)) * ROWB + (lane >> 4) * 16);
    const uint32_t bLm = (uint32_t)((wc * 32 + (lane & 7) + ((lane >> 4) << 3)) * ROWB
                                    + ((lane >> 3) & 1) * 16);

    auto load_chunk = [&](int stage, int k0) {
        const uint32_t st = sb + (uint32_t)(stage * STAGEB);
        cpa16(st + dOff1,                 Ah0 + k0,           16u);
        cpa16(st + dOff2,                 Ah0 + k0 + 64L * K, 16u);
        cpa16(st + COMPB + dOff1,         Al0 + k0,           16u);
        cpa16(st + COMPB + dOff2,         Al0 + k0 + 64L * K, 16u);
        cpa16(st + 2 * COMPB + dOff1,     Bh1 + k0,           bs1);
        cpa16(st + 2 * COMPB + dOff2,     Bh2 + k0,           bs2);
        cpa16(st + 3 * COMPB + dOff1,     Bl1 + k0,           bs1);
        cpa16(st + 3 * COMPB + dOff2,     Bl2 + k0,           bs2);
        cpa_commit();
    };

    load_chunk(0, 0);

    for (int c = 0; c < NC; c++) {
        const int buf = c & 1;
        cpa_wait<0>();                     // chunk c resident
        __syncthreads();                   // ALSO fences buf^1 reuse
        if (c + 1 < NC) load_chunk(buf ^ 1, (c + 1) * 32);

        const uint32_t st = sb + (uint32_t)(buf * STAGEB);
        const uint32_t aHB = st + aLm;
        const uint32_t aLB = st + COMPB + aLm;
        const uint32_t bHB = st + 2 * COMPB + bLm;
        const uint32_t bLB = st + 3 * COMPB + bLm;

#pragma unroll
        for (int kk = 0; kk < 2; kk++) {
            uint32_t bh[4][2], bl[4][2];
#pragma unroll
            for (int pr = 0; pr < 2; pr++) {
                const uint32_t o = (uint32_t)(pr * 16 * ROWB + kk * 32);
                uint32_t r4[4];
                ldsm4(r4, bHB + o);
                bh[pr * 2][0] = r4[0]; bh[pr * 2][1] = r4[1];
                bh[pr * 2 + 1][0] = r4[2]; bh[pr * 2 + 1][1] = r4[3];
                ldsm4(r4, bLB + o);
                bl[pr * 2][0] = r4[0]; bl[pr * 2][1] = r4[1];
                bl[pr * 2 + 1][0] = r4[2]; bl[pr * 2 + 1][1] = r4[3];
            }
#pragma unroll
            for (int mp = 0; mp < 2; mp++) {
                const int m0 = mp * 2, m1 = mp * 2 + 1;
                const uint32_t o0 = (uint32_t)(m0 * 16 * ROWB + kk * 32);
                const uint32_t o1 = (uint32_t)(m1 * 16 * ROWB + kk * 32);
                uint32_t ah0[4], al0[4], ah1[4], al1[4];
                ldsm4(ah0, aHB + o0);
                ldsm4(al0, aLB + o0);
                ldsm4(ah1, aHB + o1);
                ldsm4(al1, aLB + o1);
#pragma unroll
                for (int nt = 0; nt < 4; nt++) mma_f16(acc[m0][nt], ah0, bh[nt]);
#pragma unroll
                for (int nt = 0; nt < 4; nt++) mma_f16(acc[m1][nt], ah1, bh[nt]);
#pragma unroll
                for (int nt = 0; nt < 4; nt++) mma_f16(acc[m0][nt], al0, bh[nt]);
#pragma unroll
                for (int nt = 0; nt < 4; nt++) mma_f16(acc[m1][nt], al1, bh[nt]);
#pragma unroll
                for (int nt = 0; nt < 4; nt++) mma_f16(acc[m0][nt], ah0, bl[nt]);
#pragma unroll
                for (int nt = 0; nt < 4; nt++) mma_f16(acc[m1][nt], ah1, bl[nt]);
            }
        }
    }

    // ---- epilogue ----
    const int rbase = row0 + wr * 64 + (lane >> 2);
    const int cbase = col0 + wc * 32 + (lane & 3) * 2;
#pragma unroll
    for (int nt = 0; nt < 4; nt++) {
        const int cc = cbase + nt * 8;
        if (cc < N) {
            const float bx = bias[cc], by = bias[cc + 1];
#pragma unroll
            for (int mt = 0; mt < 4; mt++) {
                const int r = rbase + mt * 16;
                float v[4];
                v[0] = acc[mt][nt][0] + bx; v[1] = acc[mt][nt][1] + by;
                v[2] = acc[mt][nt][2] + bx; v[3] = acc[mt][nt][3] + by;
                if (RELU) {
#pragma unroll
                    for (int q = 0; q < 4; q++) v[q] = fmaxf(v[q], 0.f);
                }
                if (SPLIT_OUT) {
                    __half h0, l0, h1x, l1, h2x, l2, h3, l3;
                    split_h(v[0], h0, l0); split_h(v[1], h1x, l1);
                    split_h(v[2], h2x, l2); split_h(v[3], h3, l3);
                    *(__half2*)&Ch[(long)r * N + cc]       = __halves2half2(h0, h1x);
                    *(__half2*)&Cl[(long)r * N + cc]       = __halves2half2(l0, l1);
                    *(__half2*)&Ch[(long)(r + 8) * N + cc] = __halves2half2(h2x, h3);
                    *(__half2*)&Cl[(long)(r + 8) * N + cc] = __halves2half2(l2, l3);
                } else if (HALF_OUT) {
                    *(__half2*)&Ch[(long)r * N + cc]       = __floats2half2_rn(v[0], v[1]);
                    *(__half2*)&Ch[(long)(r + 8) * N + cc] = __floats2half2_rn(v[2], v[3]);
                } else {
                    *(float2*)&Cf[(long)r * N + cc]       = make_float2(v[0], v[1]);
                    *(float2*)&Cf[(long)(r + 8) * N + cc] = make_float2(v[2], v[3]);
                }
            }
        }
    }
}

// ---------------------------------------------------------------------------
__global__ __launch_bounds__(256) void split_kernel(
    const float* __restrict__ in, __half* __restrict__ hi, __half* __restrict__ lo,
    int n4)
{
    int i = blockIdx.x * 256 + threadIdx.x;
    if (i >= n4) return;
    float4 v = ((const float4*)in)[i];
    __half h0, l0, h1, l1, h2, l2, h3, l3;
    split_h(v.x, h0, l0); split_h(v.y, h1, l1);
    split_h(v.z, h2, l2); split_h(v.w, h3, l3);
    ((__half2*)hi)[i * 2]     = __halves2half2(h0, h1);
    ((__half2*)hi)[i * 2 + 1] = __halves2half2(h2, h3);
    ((__half2*)lo)[i * 2]     = __halves2half2(l0, l1);
    ((__half2*)lo)[i * 2 + 1] = __halves2half2(l2, l3);
}

// ---------------------------------------------------------------------------
__global__ void transpose_split_all(
    const float* __restrict__ W1, __half* __restrict__ T1h, __half* __restrict__ T1l,
    const float* __restrict__ W2, __half* __restrict__ T2h, __half* __restrict__ T2l,
    const float* __restrict__ W3, __half* __restrict__ T3h, __half* __restrict__ T3l)
{
    const float* W; __half* Th; __half* Tl; int R, C;
    if (blockIdx.z == 0)      { W = W1; Th = T1h; Tl = T1l; R = FDIM; C = HDIM; }
    else if (blockIdx.z == 1) { W = W2; Th = T2h; Tl = T2l; R = HDIM; C = HDIM; }
    else                      { W = W3; Th = T3h; Tl = T3l; R = HDIM; C = FDIM; }
    if ((int)blockIdx.x * 32 >= C || (int)blockIdx.y * 32 >= R) return;

    __shared__ float tb[32][33];
    int c = blockIdx.x * 32 + threadIdx.x;
    int r0 = blockIdx.y * 32;
    for (int j = threadIdx.y; j < 32; j += 8)
        tb[j][threadIdx.x] = W[(r0 + j) * C + c];
    __syncthreads();
    int rOut = r0 + threadIdx.x;
    int cBase = blockIdx.x * 32;
    for (int j = threadIdx.y; j < 32; j += 8) {
        float v = tb[threadIdx.x][j];
        __half h, l;
        split_h(v, h, l);
        Th[(long)(cBase + j) * R + rOut] = h;
        Tl[(long)(cBase + j) * R + rOut] = l;
    }
}

// ---------------------------------------------------------------------------
__global__ __launch_bounds__(256) void cls_kernel2(
    const float* __restrict__ ab, int* __restrict__ cls)
{
    int i = blockIdx.x * 256 + threadIdx.x;   // pair index
    if (i >= NPIX / 2) return;
    const float4* p = (const float4*)(ab + (long)i * 12);
    float4 v0 = p[0], v1 = p[1], v2 = p[2];
    float a[6] = { v0.x, v0.y, v0.z, v0.w, v1.x, v1.y };
    float b[6] = { v1.z, v1.w, v2.x, v2.y, v2.z, v2.w };
    int ba = 0, bb = 0;
    float ma = a[0], mb = b[0];
#pragma unroll
    for (int q = 1; q < 6; q++) {
        if (a[q] > ma) { ma = a[q]; ba = q; }
        if (b[q] > mb) { mb = b[q]; bb = q; }
    }
    cls[i * 2] = ba;
    cls[i * 2 + 1] = bb;
}

// ---------------------------------------------------------------------------
// Endmember partials from fp16 logits; two independent online-softmax chains
// (even/odd pixels) to halve the serial latency chain, merged at the end.
// grid NCHUNK blocks x 224 threads; each block: 128 consecutive pixels.
// ---------------------------------------------------------------------------
__global__ __launch_bounds__(224) void endmember_part2(
    const __half* __restrict__ logits, const float* __restrict__ Y,
    const int* __restrict__ cls)
{
    const int blk = blockIdx.x;
    const int t = threadIdx.x;              // feature
    const int n0 = blk * (NPIX / NCHUNK);   // 128 pixels per chunk

    __shared__ int scls[NPIX / NCHUNK];
    for (int i = t; i < NPIX / NCHUNK; i += 224) scls[i] = cls[n0 + i];
    __syncthreads();

    float m[2][PDIM], s[2][PDIM], sy[2][PDIM];
#pragma unroll
    for (int q = 0; q < 2; q++)
#pragma unroll
        for (int p = 0; p < PDIM; p++) {
            m[q][p] = -FLT_MAX; s[q][p] = 0.f; sy[q][p] = 0.f;
        }

    for (int i = 0; i < NPIX / NCHUNK; i += 2) {
#pragma unroll
        for (int q = 0; q < 2; q++) {
            const int r = i + q;
            const int c = scls[r];
            const long off = (long)(n0 + r) * FDIM + t;
            const float l = __half2float(logits[off]);
            const float y = Y[off];
            float mc = m[q][0], sc = s[q][0], syc = sy[q][0];
#pragma unroll
            for (int p = 1; p < PDIM; p++) {
                bool e = (c == p);
                mc = e ? m[q][p] : mc; sc = e ? s[q][p] : sc; syc = e ? sy[q][p] : syc;
            }
            float mn  = fmaxf(mc, l);
            float sca = __expf(mc - mn);
            float ea  = __expf(l - mn);
            float sn  = sc * sca + ea;
            float syn = syc * sca + ea * y;
#pragma unroll
            for (int p = 0; p < PDIM; p++) {
                bool e = (c == p);
                m[q][p] = e ? mn : m[q][p];
                s[q][p] = e ? sn : s[q][p];
                sy[q][p] = e ? syn : sy[q][p];
            }
        }
    }

#pragma unroll
    for (int p = 0; p < PDIM; p++) {
        float mx = fmaxf(m[0][p], m[1][p]);
        float e0 = __expf(m[0][p] - mx);
        float e1 = __expf(m[1][p] - mx);
        float S  = s[0][p] * e0 + s[1][p] * e1;
        float SY = sy[0][p] * e0 + sy[1][p] * e1;
        long base = (((long)blk * PDIM + p) * 3) * FDIM + t;
        g_part[base]            = mx;
        g_part[base + FDIM]     = S;
        g_part[base + 2 * FDIM] = SY;
    }
}

// grid PDIM blocks x 224 threads: merge per-rowblock partials
__global__ __launch_bounds__(224) void endmember_combine2(float* __restrict__ Mo) {
    const int p = blockIdx.x;
    const int f = threadIdx.x;
    float m = -FLT_MAX, s = 0.f, sy = 0.f;
    for (int b = 0; b < NCHUNK; b++) {
        long base = (((long)b * PDIM + p) * 3) * FDIM + f;
        float m2 = g_part[base];
        float s2 = g_part[base + FDIM];
        float sy2 = g_part[base + 2 * FDIM];
        float mx = fmaxf(m, m2);
        float e1 = __expf(m - mx), e2 = __expf(m2 - mx);
        s  = s * e1 + s2 * e2;
        sy = sy * e1 + sy2 * e2;
        m = mx;
    }
    Mo[p * FDIM + f] = (s > 0.f) ? (sy / s) : 0.0f;
}

// ---------------------------------------------------------------------------
__global__ __launch_bounds__(224) void yhat_kernel2(
    const float* __restrict__ ab, const float* __restrict__ M,
    float* __restrict__ out)
{
    constexpr int CH = NPIX / NCHUNK;  // 128
    __shared__ float sM[PDIM * FDIM];
    __shared__ float sab[CH * PDIM];
    const int t = threadIdx.x;
    const int n0 = blockIdx.x * CH;
    for (int i = t; i < PDIM * FDIM; i += 224) sM[i] = M[i];
    for (int i = t; i < CH * PDIM; i += 224) sab[i] = ab[(long)n0 * PDIM + i];
    __syncthreads();

    for (int i = 0; i < CH; i++) {
        float acc = 0.f;
#pragma unroll
        for (int p = 0; p < PDIM; p++) acc += sab[i * PDIM + p] * sM[p * FDIM + t];
        out[(long)(n0 + i) * FDIM + t] = acc;
    }
}

// ---------------------------------------------------------------------------
extern "C" void kernel_launch(void* const* d_in, const int* in_sizes, int n_in,
                              void* d_out, int out_size)
{
    const float* ab = (const float*)d_in[0];
    const float* Y  = (const float*)d_in[1];
    const float* W1 = (const float*)d_in[2];
    const float* b1 = (const float*)d_in[3];
    const float* W2 = (const float*)d_in[4];
    const float* b2 = (const float*)d_in[5];
    const float* W3 = (const float*)d_in[6];
    const float* b3 = (const float*)d_in[7];
    float* out = (float*)d_out;

    __half *yh, *yl, *h1h, *h1l, *h2h, *h2l, *lg;
    __half *w1h, *w1l, *w2h, *w2l, *w3h, *w3l;
    float *M;
    int* cls;
    cudaGetSymbolAddress((void**)&yh,  g_Yh);
    cudaGetSymbolAddress((void**)&yl,  g_Yl);
    cudaGetSymbolAddress((void**)&h1h, g_h1h);
    cudaGetSymbolAddress((void**)&h1l, g_h1l);
    cudaGetSymbolAddress((void**)&h2h, g_h2h);
    cudaGetSymbolAddress((void**)&h2l, g_h2l);
    cudaGetSymbolAddress((void**)&w1h, g_W1Th);
    cudaGetSymbolAddress((void**)&w1l, g_W1Tl);
    cudaGetSymbolAddress((void**)&w2h, g_W2Th);
    cudaGetSymbolAddress((void**)&w2l, g_W2Tl);
    cudaGetSymbolAddress((void**)&w3h, g_W3Th);
    cudaGetSymbolAddress((void**)&w3l, g_W3Tl);
    cudaGetSymbolAddress((void**)&lg,  g_logits);
    cudaGetSymbolAddress((void**)&cls, g_cls);
    cudaGetSymbolAddress((void**)&M,   g_M);

    constexpr int SMEM = 2 * 4 * 128 * 80;  // 81920 bytes (2 stages)
    cudaFuncSetAttribute(mma_gemm_f16<HDIM, FDIM, true, true, false>,
                         cudaFuncAttributeMaxDynamicSharedMemorySize, SMEM);
    cudaFuncSetAttribute(mma_gemm_f16<HDIM, HDIM, true, true, false>,
                         cudaFuncAttributeMaxDynamicSharedMemorySize, SMEM);
    cudaFuncSetAttribute(mma_gemm_f16<FDIM, HDIM, false, false, true>,
                         cudaFuncAttributeMaxDynamicSharedMemorySize, SMEM);

    // prep
    split_kernel<<<(NPIX * FDIM / 4 + 255) / 256, 256>>>(Y, yh, yl, NPIX * FDIM / 4);
    transpose_split_all<<<dim3(8, 8, 3), dim3(32, 8)>>>(
        W1, w1h, w1l, W2, w2h, w2l, W3, w3h, w3l);
    cls_kernel2<<<(NPIX / 2 + 255) / 256, 256>>>(ab, cls);

    // GEMM chain (128x128 tiles); GEMM3 writes fp16 logits
    mma_gemm_f16<HDIM, FDIM, true, true, false><<<dim3(2, NPIX / 128), 256, SMEM>>>(
        yh, yl, w1h, w1l, b1, nullptr, h1h, h1l);
    mma_gemm_f16<HDIM, HDIM, true, true, false><<<dim3(2, NPIX / 128), 256, SMEM>>>(
        h1h, h1l, w2h, w2l, b2, nullptr, h2h, h2l);
    mma_gemm_f16<FDIM, HDIM, false, false, true><<<dim3(2, NPIX / 128), 256, SMEM>>>(
        h2h, h2l, w3h, w3l, b3, nullptr, lg, nullptr);

    // masked per-class softmax endmembers
    endmember_part2<<<NCHUNK, 224>>>(lg, Y, cls);
    endmember_combine2<<<PDIM, 224>>>(M);

    // reconstruction
    yhat_kernel2<<<NCHUNK, 224>>>(ab, M, out);
}

// round 14
// speedup vs baseline: 1.2532x; 1.1212x over previous
#include <cuda_runtime.h>
#include <cuda_fp16.h>
#include <cstdint>
#include <float.h>

#define NPIX 65536
#define FDIM 224
#define PDIM 6
#define HDIM 256
#define NCHUNK 512          // pixel row-blocks (128 px each)

// ------------------------- static device scratch ---------------------------
__device__ __half g_Yh[NPIX * FDIM];
__device__ __half g_Yl[NPIX * FDIM];
__device__ __half g_h1h[NPIX * HDIM];
__device__ __half g_h1l[NPIX * HDIM];
__device__ __half g_h2h[NPIX * HDIM];
__device__ __half g_h2l[NPIX * HDIM];
__device__ __half g_logits[NPIX * FDIM];   // fp16 logits (hi)
__device__ int    g_cls[NPIX];
__device__ float  g_M[PDIM * FDIM];
__device__ __half g_W1Th[HDIM * FDIM];
__device__ __half g_W1Tl[HDIM * FDIM];
__device__ __half g_W2Th[HDIM * HDIM];
__device__ __half g_W2Tl[HDIM * HDIM];
__device__ __half g_W3Th[FDIM * HDIM];
__device__ __half g_W3Tl[FDIM * HDIM];
// per-rowblock partials: [rowblk][class][{s,sy}][FDIM]  (plain-exp sums)
__device__ float  g_part[NCHUNK * PDIM * 2 * FDIM];

// ------------------------------ PTX helpers --------------------------------
__device__ __forceinline__ uint32_t smem_u32(const void* p) {
    uint32_t a;
    asm("{ .reg .u64 t; cvta.to.shared.u64 t, %1; cvt.u32.u64 %0, t; }"
        : "=r"(a) : "l"(p));
    return a;
}
__device__ __forceinline__ void cpa16(uint32_t dst, const void* src, uint32_t sz) {
    asm volatile("cp.async.cg.shared.global [%0], [%1], 16, %2;"
                 :: "r"(dst), "l"(src), "r"(sz) : "memory");
}
__device__ __forceinline__ void cpa_commit() {
    asm volatile("cp.async.commit_group;" ::: "memory");
}
template <int n> __device__ __forceinline__ void cpa_wait() {
    asm volatile("cp.async.wait_group %0;" :: "n"(n) : "memory");
}
__device__ __forceinline__ void ldsm4(uint32_t* r, uint32_t addr) {
    asm volatile("ldmatrix.sync.aligned.m8n8.x4.shared.b16 {%0,%1,%2,%3}, [%4];"
                 : "=r"(r[0]), "=r"(r[1]), "=r"(r[2]), "=r"(r[3]) : "r"(addr));
}
__device__ __forceinline__ void mma_f16(float* d, const uint32_t* a, const uint32_t* b) {
    asm volatile(
        "mma.sync.aligned.m16n8k16.row.col.f32.f16.f16.f32 "
        "{%0,%1,%2,%3}, {%4,%5,%6,%7}, {%8,%9}, {%0,%1,%2,%3};"
        : "+f"(d[0]), "+f"(d[1]), "+f"(d[2]), "+f"(d[3])
        : "r"(a[0]), "r"(a[1]), "r"(a[2]), "r"(a[3]), "r"(b[0]), "r"(b[1]));
}
__device__ __forceinline__ void split_h(float v, __half& hi, __half& lo) {
    hi = __float2half_rn(v);
    lo = __float2half_rn(v - __half2float(hi));
}

// ---------------------------------------------------------------------------
// fp16x3 mma.sync GEMM: C = act(A @ BT^T + bias), fp32-accurate.
// Block 128x128, 8 warps (2x4), warp tile 64x32, K chunks of 32, 2-stage
// cp.async, one __syncthreads per chunk, paired-mt MMA schedule (champion).
// SPLIT_OUT: hi/lo fp16 pair outputs (chained layers).
// HALF_OUT: single fp16 output (logits).
// ---------------------------------------------------------------------------
template <int N, int K, bool RELU, bool SPLIT_OUT, bool HALF_OUT>
__global__ __launch_bounds__(256, 2) void mma_gemm_f16(
    const __half* __restrict__ Ah, const __half* __restrict__ Al,
    const __half* __restrict__ Bh, const __half* __restrict__ Bl,
    const float* __restrict__ bias,
    float* __restrict__ Cf, __half* __restrict__ Ch, __half* __restrict__ Cl)
{
    constexpr int NC = K / 32;
    constexpr int ROWB = 80;               // bytes/row: 64B data + 16B pad
    constexpr int COMPB = 128 * ROWB;      // 10240 per component tile
    constexpr int STAGEB = 4 * COMPB;      // 40960: [Ah][Al][Bh][Bl]

    extern __shared__ char sh[];
    const uint32_t sb = smem_u32(sh);

    const int t = threadIdx.x;
    const int lane = t & 31, wid = t >> 5;
    const int wr = wid >> 2;               // 0..1
    const int wc = wid & 3;                // 0..3
    const int row0 = blockIdx.y * 128;
    const int col0 = blockIdx.x * 128;

    float acc[4][4][4];
#pragma unroll
    for (int i = 0; i < 4; i++)
#pragma unroll
        for (int j = 0; j < 4; j++)
#pragma unroll
            for (int k = 0; k < 4; k++) acc[i][j][k] = 0.0f;

    const int cr = t >> 2;
    const int g  = t & 3;
    const uint32_t dOff1 = (uint32_t)(cr * ROWB + g * 16);
    const uint32_t dOff2 = dOff1 + (uint32_t)(64 * ROWB);

    const __half* Ah0 = Ah + (long)(row0 + cr) * K + g * 8;
    const __half* Al0 = Al + (long)(row0 + cr) * K + g * 8;
    int bn1 = col0 + cr, bn2 = col0 + cr + 64;
    const uint32_t bs1 = (bn1 < N) ? 16u : 0u;
    const uint32_t bs2 = (bn2 < N) ? 16u : 0u;
    if (bn1 >= N) bn1 = N - 1;
    if (bn2 >= N) bn2 = N - 1;
    const __half* Bh1 = Bh + (long)bn1 * K + g * 8;
    const __half* Bh2 = Bh + (long)bn2 * K + g * 8;
    const __half* Bl1 = Bl + (long)bn1 * K + g * 8;
    const __half* Bl2 = Bl + (long)bn2 * K + g * 8;

    const uint32_t aLm = (uint32_t)((wr * 64 + (lane & 15)) * ROWB + (lane >> 4) * 16);
    const uint32_t bLm = (uint32_t)((wc * 32 + (lane & 7) + ((lane >> 4) << 3)) * ROWB
                                    + ((lane >> 3) & 1) * 16);

    auto load_chunk = [&](int stage, int k0) {
        const uint32_t st = sb + (uint32_t)(stage * STAGEB);
        cpa16(st + dOff1,                 Ah0 + k0,           16u);
        cpa16(st + dOff2,                 Ah0 + k0 + 64L * K, 16u);
        cpa16(st + COMPB + dOff1,         Al0 + k0,           16u);
        cpa16(st + COMPB + dOff2,         Al0 + k0 + 64L * K, 16u);
        cpa16(st + 2 * COMPB + dOff1,     Bh1 + k0,           bs1);
        cpa16(st + 2 * COMPB + dOff2,     Bh2 + k0,           bs2);
        cpa16(st + 3 * COMPB + dOff1,     Bl1 + k0,           bs1);
        cpa16(st + 3 * COMPB + dOff2,     Bl2 + k0,           bs2);
        cpa_commit();
    };

    load_chunk(0, 0);

    for (int c = 0; c < NC; c++) {
        const int buf = c & 1;
        cpa_wait<0>();                     // chunk c resident
        __syncthreads();                   // ALSO fences buf^1 reuse
        if (c + 1 < NC) load_chunk(buf ^ 1, (c + 1) * 32);

        const uint32_t st = sb + (uint32_t)(buf * STAGEB);
        const uint32_t aHB = st + aLm;
        const uint32_t aLB = st + COMPB + aLm;
        const uint32_t bHB = st + 2 * COMPB + bLm;
        const uint32_t bLB = st + 3 * COMPB + bLm;

#pragma unroll
        for (int kk = 0; kk < 2; kk++) {
            uint32_t bh[4][2], bl[4][2];
#pragma unroll
            for (int pr = 0; pr < 2; pr++) {
                const uint32_t o = (uint32_t)(pr * 16 * ROWB + kk * 32);
                uint32_t r4[4];
                ldsm4(r4, bHB + o);
                bh[pr * 2][0] = r4[0]; bh[pr * 2][1] = r4[1];
                bh[pr * 2 + 1][0] = r4[2]; bh[pr * 2 + 1][1] = r4[3];
                ldsm4(r4, bLB + o);
                bl[pr * 2][0] = r4[0]; bl[pr * 2][1] = r4[1];
                bl[pr * 2 + 1][0] = r4[2]; bl[pr * 2 + 1][1] = r4[3];
            }
#pragma unroll
            for (int mp = 0; mp < 2; mp++) {
                const int m0 = mp * 2, m1 = mp * 2 + 1;
                const uint32_t o0 = (uint32_t)(m0 * 16 * ROWB + kk * 32);
                const uint32_t o1 = (uint32_t)(m1 * 16 * ROWB + kk * 32);
                uint32_t ah0[4], al0[4], ah1[4], al1[4];
                ldsm4(ah0, aHB + o0);
                ldsm4(al0, aLB + o0);
                ldsm4(ah1, aHB + o1);
                ldsm4(al1, aLB + o1);
#pragma unroll
                for (int nt = 0; nt < 4; nt++) mma_f16(acc[m0][nt], ah0, bh[nt]);
#pragma unroll
                for (int nt = 0; nt < 4; nt++) mma_f16(acc[m1][nt], ah1, bh[nt]);
#pragma unroll
                for (int nt = 0; nt < 4; nt++) mma_f16(acc[m0][nt], al0, bh[nt]);
#pragma unroll
                for (int nt = 0; nt < 4; nt++) mma_f16(acc[m1][nt], al1, bh[nt]);
#pragma unroll
                for (int nt = 0; nt < 4; nt++) mma_f16(acc[m0][nt], ah0, bl[nt]);
#pragma unroll
                for (int nt = 0; nt < 4; nt++) mma_f16(acc[m1][nt], ah1, bl[nt]);
            }
        }
    }

    // ---- epilogue ----
    const int rbase = row0 + wr * 64 + (lane >> 2);
    const int cbase = col0 + wc * 32 + (lane & 3) * 2;
#pragma unroll
    for (int nt = 0; nt < 4; nt++) {
        const int cc = cbase + nt * 8;
        if (cc < N) {
            const float bx = bias[cc], by = bias[cc + 1];
#pragma unroll
            for (int mt = 0; mt < 4; mt++) {
                const int r = rbase + mt * 16;
                float v[4];
                v[0] = acc[mt][nt][0] + bx; v[1] = acc[mt][nt][1] + by;
                v[2] = acc[mt][nt][2] + bx; v[3] = acc[mt][nt][3] + by;
                if (RELU) {
#pragma unroll
                    for (int q = 0; q < 4; q++) v[q] = fmaxf(v[q], 0.f);
                }
                if (SPLIT_OUT) {
                    __half h0, l0, h1x, l1, h2x, l2, h3, l3;
                    split_h(v[0], h0, l0); split_h(v[1], h1x, l1);
                    split_h(v[2], h2x, l2); split_h(v[3], h3, l3);
                    *(__half2*)&Ch[(long)r * N + cc]       = __halves2half2(h0, h1x);
                    *(__half2*)&Cl[(long)r * N + cc]       = __halves2half2(l0, l1);
                    *(__half2*)&Ch[(long)(r + 8) * N + cc] = __halves2half2(h2x, h3);
                    *(__half2*)&Cl[(long)(r + 8) * N + cc] = __halves2half2(l2, l3);
                } else if (HALF_OUT) {
                    *(__half2*)&Ch[(long)r * N + cc]       = __floats2half2_rn(v[0], v[1]);
                    *(__half2*)&Ch[(long)(r + 8) * N + cc] = __floats2half2_rn(v[2], v[3]);
                } else {
                    *(float2*)&Cf[(long)r * N + cc]       = make_float2(v[0], v[1]);
                    *(float2*)&Cf[(long)(r + 8) * N + cc] = make_float2(v[2], v[3]);
                }
            }
        }
    }
}

// ---------------------------------------------------------------------------
__global__ __launch_bounds__(256) void split_kernel(
    const float* __restrict__ in, __half* __restrict__ hi, __half* __restrict__ lo,
    int n4)
{
    int i = blockIdx.x * 256 + threadIdx.x;
    if (i >= n4) return;
    float4 v = ((const float4*)in)[i];
    __half h0, l0, h1, l1, h2, l2, h3, l3;
    split_h(v.x, h0, l0); split_h(v.y, h1, l1);
    split_h(v.z, h2, l2); split_h(v.w, h3, l3);
    ((__half2*)hi)[i * 2]     = __halves2half2(h0, h1);
    ((__half2*)hi)[i * 2 + 1] = __halves2half2(h2, h3);
    ((__half2*)lo)[i * 2]     = __halves2half2(l0, l1);
    ((__half2*)lo)[i * 2 + 1] = __halves2half2(l2, l3);
}

// ---------------------------------------------------------------------------
__global__ void transpose_split_all(
    const float* __restrict__ W1, __half* __restrict__ T1h, __half* __restrict__ T1l,
    const float* __restrict__ W2, __half* __restrict__ T2h, __half* __restrict__ T2l,
    const float* __restrict__ W3, __half* __restrict__ T3h, __half* __restrict__ T3l)
{
    const float* W; __half* Th; __half* Tl; int R, C;
    if (blockIdx.z == 0)      { W = W1; Th = T1h; Tl = T1l; R = FDIM; C = HDIM; }
    else if (blockIdx.z == 1) { W = W2; Th = T2h; Tl = T2l; R = HDIM; C = HDIM; }
    else                      { W = W3; Th = T3h; Tl = T3l; R = HDIM; C = FDIM; }
    if ((int)blockIdx.x * 32 >= C || (int)blockIdx.y * 32 >= R) return;

    __shared__ float tb[32][33];
    int c = blockIdx.x * 32 + threadIdx.x;
    int r0 = blockIdx.y * 32;
    for (int j = threadIdx.y; j < 32; j += 8)
        tb[j][threadIdx.x] = W[(r0 + j) * C + c];
    __syncthreads();
    int rOut = r0 + threadIdx.x;
    int cBase = blockIdx.x * 32;
    for (int j = threadIdx.y; j < 32; j += 8) {
        float v = tb[threadIdx.x][j];
        __half h, l;
        split_h(v, h, l);
        Th[(long)(cBase + j) * R + rOut] = h;
        Tl[(long)(cBase + j) * R + rOut] = l;
    }
}

// ---------------------------------------------------------------------------
__global__ __launch_bounds__(256) void cls_kernel2(
    const float* __restrict__ ab, int* __restrict__ cls)
{
    int i = blockIdx.x * 256 + threadIdx.x;   // pair index
    if (i >= NPIX / 2) return;
    const float4* p = (const float4*)(ab + (long)i * 12);
    float4 v0 = p[0], v1 = p[1], v2 = p[2];
    float a[6] = { v0.x, v0.y, v0.z, v0.w, v1.x, v1.y };
    float b[6] = { v1.z, v1.w, v2.x, v2.y, v2.z, v2.w };
    int ba = 0, bb = 0;
    float ma = a[0], mb = b[0];
#pragma unroll
    for (int q = 1; q < 6; q++) {
        if (a[q] > ma) { ma = a[q]; ba = q; }
        if (b[q] > mb) { mb = b[q]; bb = q; }
    }
    cls[i * 2] = ba;
    cls[i * 2 + 1] = bb;
}

// ---------------------------------------------------------------------------
// Endmember partials: PLAIN-EXP sums (no max-subtraction, no serial chain).
// Valid because |logits| << 80 (MLP outputs, O(1) scale) -> no fp32 overflow.
// s[p] += e^l, sy[p] += e^l * y; per-class FADD chains are independent and
// pipeline fully. Reads fp16 logits + fp16 Y (hi). grid NCHUNK x 224 threads.
// ---------------------------------------------------------------------------
__global__ __launch_bounds__(224) void endmember_part3(
    const __half* __restrict__ logits, const __half* __restrict__ Yh,
    const int* __restrict__ cls)
{
    const int blk = blockIdx.x;
    const int t = threadIdx.x;              // feature
    const int n0 = blk * (NPIX / NCHUNK);   // 128 pixels per chunk

    __shared__ int scls[NPIX / NCHUNK];
    for (int i = t; i < NPIX / NCHUNK; i += 224) scls[i] = cls[n0 + i];
    __syncthreads();

    float s[PDIM], sy[PDIM];
#pragma unroll
    for (int p = 0; p < PDIM; p++) { s[p] = 0.f; sy[p] = 0.f; }

#pragma unroll 4
    for (int i = 0; i < NPIX / NCHUNK; i++) {
        const int c = scls[i];
        const long off = (long)(n0 + i) * FDIM + t;
        const float l = __half2float(logits[off]);
        const float y = __half2float(Yh[off]);
        const float e = __expf(l);
        const float ey = e * y;
#pragma unroll
        for (int p = 0; p < PDIM; p++) {
            const bool msk = (c == p);
            s[p]  += msk ? e  : 0.f;
            sy[p] += msk ? ey : 0.f;
        }
    }

#pragma unroll
    for (int p = 0; p < PDIM; p++) {
        long base = (((long)blk * PDIM + p) * 2) * FDIM + t;
        g_part[base]        = s[p];
        g_part[base + FDIM] = sy[p];
    }
}

// grid PDIM blocks x 224 threads: sum per-rowblock partials
__global__ __launch_bounds__(224) void endmember_combine3(float* __restrict__ Mo) {
    const int p = blockIdx.x;
    const int f = threadIdx.x;
    float s = 0.f, sy = 0.f;
    for (int b = 0; b < NCHUNK; b++) {
        long base = (((long)b * PDIM + p) * 2) * FDIM + f;
        s  += g_part[base];
        sy += g_part[base + FDIM];
    }
    Mo[p * FDIM + f] = (s > 0.f) ? (sy / s) : 0.0f;
}

// ---------------------------------------------------------------------------
// Y_hat with float4 stores: 224 threads = 4 rows x 56 float4-groups per iter.
// ---------------------------------------------------------------------------
__global__ __launch_bounds__(224) void yhat_kernel3(
    const float* __restrict__ ab, const float* __restrict__ M,
    float* __restrict__ out)
{
    constexpr int CH = NPIX / NCHUNK;  // 128 rows per block
    __shared__ float sM[PDIM * FDIM];
    __shared__ float sab[CH * PDIM];
    const int t = threadIdx.x;
    const int n0 = blockIdx.x * CH;
    for (int i = t; i < PDIM * FDIM; i += 224) sM[i] = M[i];
    for (int i = t; i < CH * PDIM; i += 224) sab[i] = ab[(long)n0 * PDIM + i];
    __syncthreads();

    const float4* sM4 = (const float4*)sM;   // [PDIM][56]
    const int rsub = t / 56;                 // 0..3
    const int f4 = t - rsub * 56;            // 0..55

    for (int i = 0; i < CH / 4; i++) {
        const int r = i * 4 + rsub;
        float a0 = sab[r * PDIM + 0], a1 = sab[r * PDIM + 1];
        float a2 = sab[r * PDIM + 2], a3 = sab[r * PDIM + 3];
        float a4 = sab[r * PDIM + 4], a5 = sab[r * PDIM + 5];
        float4 m0 = sM4[0 * 56 + f4], m1 = sM4[1 * 56 + f4];
        float4 m2 = sM4[2 * 56 + f4], m3 = sM4[3 * 56 + f4];
        float4 m4 = sM4[4 * 56 + f4], m5 = sM4[5 * 56 + f4];
        float4 o;
        o.x = a0 * m0.x + a1 * m1.x + a2 * m2.x + a3 * m3.x + a4 * m4.x + a5 * m5.x;
        o.y = a0 * m0.y + a1 * m1.y + a2 * m2.y + a3 * m3.y + a4 * m4.y + a5 * m5.y;
        o.z = a0 * m0.z + a1 * m1.z + a2 * m2.z + a3 * m3.z + a4 * m4.z + a5 * m5.z;
        o.w = a0 * m0.w + a1 * m1.w + a2 * m2.w + a3 * m3.w + a4 * m4.w + a5 * m5.w;
        *(float4*)&out[(long)(n0 + r) * FDIM + f4 * 4] = o;
    }
}

// ---------------------------------------------------------------------------
extern "C" void kernel_launch(void* const* d_in, const int* in_sizes, int n_in,
                              void* d_out, int out_size)
{
    const float* ab = (const float*)d_in[0];
    const float* Y  = (const float*)d_in[1];
    const float* W1 = (const float*)d_in[2];
    const float* b1 = (const float*)d_in[3];
    const float* W2 = (const float*)d_in[4];
    const float* b2 = (const float*)d_in[5];
    const float* W3 = (const float*)d_in[6];
    const float* b3 = (const float*)d_in[7];
    float* out = (float*)d_out;

    __half *yh, *yl, *h1h, *h1l, *h2h, *h2l, *lg;
    __half *w1h, *w1l, *w2h, *w2l, *w3h, *w3l;
    float *M;
    int* cls;
    cudaGetSymbolAddress((void**)&yh,  g_Yh);
    cudaGetSymbolAddress((void**)&yl,  g_Yl);
    cudaGetSymbolAddress((void**)&h1h, g_h1h);
    cudaGetSymbolAddress((void**)&h1l, g_h1l);
    cudaGetSymbolAddress((void**)&h2h, g_h2h);
    cudaGetSymbolAddress((void**)&h2l, g_h2l);
    cudaGetSymbolAddress((void**)&w1h, g_W1Th);
    cudaGetSymbolAddress((void**)&w1l, g_W1Tl);
    cudaGetSymbolAddress((void**)&w2h, g_W2Th);
    cudaGetSymbolAddress((void**)&w2l, g_W2Tl);
    cudaGetSymbolAddress((void**)&w3h, g_W3Th);
    cudaGetSymbolAddress((void**)&w3l, g_W3Tl);
    cudaGetSymbolAddress((void**)&lg,  g_logits);
    cudaGetSymbolAddress((void**)&cls, g_cls);
    cudaGetSymbolAddress((void**)&M,   g_M);

    constexpr int SMEM = 2 * 4 * 128 * 80;  // 81920 bytes (2 stages)
    cudaFuncSetAttribute(mma_gemm_f16<HDIM, FDIM, true, true, false>,
                         cudaFuncAttributeMaxDynamicSharedMemorySize, SMEM);
    cudaFuncSetAttribute(mma_gemm_f16<HDIM, HDIM, true, true, false>,
                         cudaFuncAttributeMaxDynamicSharedMemorySize, SMEM);
    cudaFuncSetAttribute(mma_gemm_f16<FDIM, HDIM, false, false, true>,
                         cudaFuncAttributeMaxDynamicSharedMemorySize, SMEM);

    // prep
    split_kernel<<<(NPIX * FDIM / 4 + 255) / 256, 256>>>(Y, yh, yl, NPIX * FDIM / 4);
    transpose_split_all<<<dim3(8, 8, 3), dim3(32, 8)>>>(
        W1, w1h, w1l, W2, w2h, w2l, W3, w3h, w3l);
    cls_kernel2<<<(NPIX / 2 + 255) / 256, 256>>>(ab, cls);

    // GEMM chain (128x128 tiles); GEMM3 writes fp16 logits
    mma_gemm_f16<HDIM, FDIM, true, true, false><<<dim3(2, NPIX / 128), 256, SMEM>>>(
        yh, yl, w1h, w1l, b1, nullptr, h1h, h1l);
    mma_gemm_f16<HDIM, HDIM, true, true, false><<<dim3(2, NPIX / 128), 256, SMEM>>>(
        h1h, h1l, w2h, w2l, b2, nullptr, h2h, h2l);
    mma_gemm_f16<FDIM, HDIM, false, false, true><<<dim3(2, NPIX / 128), 256, SMEM>>>(
        h2h, h2l, w3h, w3l, b3, nullptr, lg, nullptr);

    // masked per-class plain-exp sums -> endmembers
    endmember_part3<<<NCHUNK, 224>>>(lg, yh, cls);
    endmember_combine3<<<PDIM, 224>>>(M);

    // reconstruction
    yhat_kernel3<<<NCHUNK, 224>>>(ab, M, out);
}

// round 16
// speedup vs baseline: 1.3079x; 1.0436x over previous
#include <cuda_runtime.h>
#include <cuda_fp16.h>
#include <cstdint>
#include <float.h>

#define NPIX 65536
#define FDIM 224
#define PDIM 6
#define HDIM 256
#define NCHUNK 512          // pixel row-blocks (128 px each)

// ------------------------- static device scratch ---------------------------
__device__ __half g_h1h[NPIX * HDIM];
__device__ __half g_h1l[NPIX * HDIM];
__device__ __half g_h2h[NPIX * HDIM];
__device__ __half g_h2l[NPIX * HDIM];
__device__ __half g_logits[NPIX * FDIM];   // fp16 logits (hi)
__device__ int    g_cls[NPIX];
__device__ float  g_M[PDIM * FDIM];
__device__ __half g_W1Th[HDIM * FDIM];
__device__ __half g_W1Tl[HDIM * FDIM];
__device__ __half g_W2Th[HDIM * HDIM];
__device__ __half g_W2Tl[HDIM * HDIM];
__device__ __half g_W3Th[FDIM * HDIM];
__device__ __half g_W3Tl[FDIM * HDIM];
// per-rowblock partials: [rowblk][class][{s,sy}][FDIM]  (plain-exp sums)
__device__ float  g_part[NCHUNK * PDIM * 2 * FDIM];

struct half2x2 { __half2 a, b; };   // 8-byte vector for STS.64

// ------------------------------ PTX helpers --------------------------------
__device__ __forceinline__ uint32_t smem_u32(const void* p) {
    uint32_t a;
    asm("{ .reg .u64 t; cvta.to.shared.u64 t, %1; cvt.u32.u64 %0, t; }"
        : "=r"(a) : "l"(p));
    return a;
}
__device__ __forceinline__ void cpa16(uint32_t dst, const void* src, uint32_t sz) {
    asm volatile("cp.async.cg.shared.global [%0], [%1], 16, %2;"
                 :: "r"(dst), "l"(src), "r"(sz) : "memory");
}
__device__ __forceinline__ void cpa_commit() {
    asm volatile("cp.async.commit_group;" ::: "memory");
}
template <int n> __device__ __forceinline__ void cpa_wait() {
    asm volatile("cp.async.wait_group %0;" :: "n"(n) : "memory");
}
__device__ __forceinline__ void ldsm4(uint32_t* r, uint32_t addr) {
    asm volatile("ldmatrix.sync.aligned.m8n8.x4.shared.b16 {%0,%1,%2,%3}, [%4];"
                 : "=r"(r[0]), "=r"(r[1]), "=r"(r[2]), "=r"(r[3]) : "r"(addr));
}
__device__ __forceinline__ void mma_f16(float* d, const uint32_t* a, const uint32_t* b) {
    asm volatile(
        "mma.sync.aligned.m16n8k16.row.col.f32.f16.f16.f32 "
        "{%0,%1,%2,%3}, {%4,%5,%6,%7}, {%8,%9}, {%0,%1,%2,%3};"
        : "+f"(d[0]), "+f"(d[1]), "+f"(d[2]), "+f"(d[3])
        : "r"(a[0]), "r"(a[1]), "r"(a[2]), "r"(a[3]), "r"(b[0]), "r"(b[1]));
}
__device__ __forceinline__ void split_h(float v, __half& hi, __half& lo) {
    hi = __float2half_rn(v);
    lo = __float2half_rn(v - __half2float(hi));
}

// ---------------------------------------------------------------------------
// fp16x3 mma.sync GEMM: C = act(A @ BT^T + bias), fp32-accurate.
// Block 128x128, 8 warps (2x4), warp tile 64x32, K chunks of 32, 2-stage
// cp.async, paired-mt MMA schedule (champion).
// SPLIT_OUT: hi/lo fp16 pair outputs (chained layers).
// HALF_OUT: single fp16 output (logits).
// CONV_A: A supplied as fp32 (Af32); staged via cp.async into a single
//   fp32 buffer and converted in-kernel to the hi/lo fp16 layout
//   (byte-identical to pre-split input) -> kills the standalone split pass.
// ---------------------------------------------------------------------------
template <int N, int K, bool RELU, bool SPLIT_OUT, bool HALF_OUT, bool CONV_A>
__global__ __launch_bounds__(256, 2) void mma_gemm_f16(
    const __half* __restrict__ Ah, const __half* __restrict__ Al,
    const __half* __restrict__ Bh, const __half* __restrict__ Bl,
    const float* __restrict__ bias,
    float* __restrict__ Cf, __half* __restrict__ Ch, __half* __restrict__ Cl,
    const float* __restrict__ Af32)
{
    constexpr int NC = K / 32;
    constexpr int ROWB = 80;               // fp16 bytes/row: 64B data + 16B pad
    constexpr int COMPB = 128 * ROWB;      // 10240 per component tile
    constexpr int STAGEB = 4 * COMPB;      // 40960: [Ah][Al][Bh][Bl]
    constexpr int A32OFF = 2 * STAGEB;     // 81920: fp32 A staging (CONV_A)
    constexpr int A32ROWB = 144;           // 128B data + 16B pad

    extern __shared__ char sh[];
    const uint32_t sb = smem_u32(sh);

    const int t = threadIdx.x;
    const int lane = t & 31, wid = t >> 5;
    const int wr = wid >> 2;               // 0..1
    const int wc = wid & 3;                // 0..3
    const int row0 = blockIdx.y * 128;
    const int col0 = blockIdx.x * 128;

    float acc[4][4][4];
#pragma unroll
    for (int i = 0; i < 4; i++)
#pragma unroll
        for (int j = 0; j < 4; j++)
#pragma unroll
            for (int k = 0; k < 4; k++) acc[i][j][k] = 0.0f;

    // ---- fp16 A cp.async mapping (non-CONV_A) ----
    const int cr = t >> 2;
    const int g  = t & 3;
    const uint32_t dOff1 = (uint32_t)(cr * ROWB + g * 16);
    const uint32_t dOff2 = dOff1 + (uint32_t)(64 * ROWB);
    const __half* Ah0 = CONV_A ? nullptr : (Ah + (long)(row0 + cr) * K + g * 8);
    const __half* Al0 = CONV_A ? nullptr : (Al + (long)(row0 + cr) * K + g * 8);

    // ---- fp32 A staging mapping (CONV_A): 4 shots of 16B per thread ----
    const int c_row = t >> 3;              // base rows for shots: c_row + 32*j
    const int c_grp = t & 7;

    // ---- B cp.async mapping ----
    int bn1 = col0 + cr, bn2 = col0 + cr + 64;
    const uint32_t bs1 = (bn1 < N) ? 16u : 0u;
    const uint32_t bs2 = (bn2 < N) ? 16u : 0u;
    if (bn1 >= N) bn1 = N - 1;
    if (bn2 >= N) bn2 = N - 1;
    const __half* Bh1 = Bh + (long)bn1 * K + g * 8;
    const __half* Bh2 = Bh + (long)bn2 * K + g * 8;
    const __half* Bl1 = Bl + (long)bn1 * K + g * 8;
    const __half* Bl2 = Bl + (long)bn2 * K + g * 8;

    const uint32_t aLm = (uint32_t)((wr * 64 + (lane & 15)) * ROWB + (lane >> 4) * 16);
    const uint32_t bLm = (uint32_t)((wc * 32 + (lane & 7) + ((lane >> 4) << 3)) * ROWB
                                    + ((lane >> 3) & 1) * 16);

    auto load_B = [&](int stage, int k0) {
        const uint32_t st = sb + (uint32_t)(stage * STAGEB);
        cpa16(st + 2 * COMPB + dOff1,     Bh1 + k0,           bs1);
        cpa16(st + 2 * COMPB + dOff2,     Bh2 + k0,           bs2);
        cpa16(st + 3 * COMPB + dOff1,     Bl1 + k0,           bs1);
        cpa16(st + 3 * COMPB + dOff2,     Bl2 + k0,           bs2);
    };
    auto load_A16 = [&](int stage, int k0) {
        const uint32_t st = sb + (uint32_t)(stage * STAGEB);
        cpa16(st + dOff1,             Ah0 + k0,           16u);
        cpa16(st + dOff2,             Ah0 + k0 + 64L * K, 16u);
        cpa16(st + COMPB + dOff1,     Al0 + k0,           16u);
        cpa16(st + COMPB + dOff2,     Al0 + k0 + 64L * K, 16u);
    };
    auto load_A32 = [&](int k0) {
#pragma unroll
        for (int j = 0; j < 4; j++) {
            const int row = c_row + 32 * j;
            cpa16(sb + (uint32_t)(A32OFF + row * A32ROWB + c_grp * 16),
                  Af32 + (long)(row0 + row) * K + k0 + c_grp * 4, 16u);
        }
    };

    // prologue: chunk 0
    if (CONV_A) load_A32(0); else load_A16(0, 0);
    load_B(0, 0);
    cpa_commit();

    for (int c = 0; c < NC; c++) {
        const int buf = c & 1;
        cpa_wait<0>();                     // chunk c resident
        __syncthreads();                   // fences buf^1 fp16 reuse + A32 reads

        if (CONV_A) {
            // convert A32(c) -> fp16 Ah/Al of stage(buf)
            char* abase = sh + buf * STAGEB;
#pragma unroll
            for (int j = 0; j < 4; j++) {
                const int row = c_row + 32 * j;
                const float4 v = *(const float4*)(sh + A32OFF + row * A32ROWB + c_grp * 16);
                __half h0, l0, h1, l1, h2, l2, h3, l3;
                split_h(v.x, h0, l0); split_h(v.y, h1, l1);
                split_h(v.z, h2, l2); split_h(v.w, h3, l3);
                half2x2 hv, lv;
                hv.a = __halves2half2(h0, h1); hv.b = __halves2half2(h2, h3);
                lv.a = __halves2half2(l0, l1); lv.b = __halves2half2(l2, l3);
                const int doff = row * ROWB + c_grp * 8;
                *(half2x2*)(abase + doff)         = hv;
                *(half2x2*)(abase + COMPB + doff) = lv;
            }
            __syncthreads();               // conversion visible; A32 free
            if (c + 1 < NC) {
                load_A32((c + 1) * 32);
                load_B(buf ^ 1, (c + 1) * 32);
                cpa_commit();
            }
        } else {
            if (c + 1 < NC) {
                load_A16(buf ^ 1, (c + 1) * 32);
                load_B(buf ^ 1, (c + 1) * 32);
                cpa_commit();
            }
        }

        const uint32_t st = sb + (uint32_t)(buf * STAGEB);
        const uint32_t aHB = st + aLm;
        const uint32_t aLB = st + COMPB + aLm;
        const uint32_t bHB = st + 2 * COMPB + bLm;
        const uint32_t bLB = st + 3 * COMPB + bLm;

#pragma unroll
        for (int kk = 0; kk < 2; kk++) {
            uint32_t bh[4][2], bl[4][2];
#pragma unroll
            for (int pr = 0; pr < 2; pr++) {
                const uint32_t o = (uint32_t)(pr * 16 * ROWB + kk * 32);
                uint32_t r4[4];
                ldsm4(r4, bHB + o);
                bh[pr * 2][0] = r4[0]; bh[pr * 2][1] = r4[1];
                bh[pr * 2 + 1][0] = r4[2]; bh[pr * 2 + 1][1] = r4[3];
                ldsm4(r4, bLB + o);
                bl[pr * 2][0] = r4[0]; bl[pr * 2][1] = r4[1];
                bl[pr * 2 + 1][0] = r4[2]; bl[pr * 2 + 1][1] = r4[3];
            }
#pragma unroll
            for (int mp = 0; mp < 2; mp++) {
                const int m0 = mp * 2, m1 = mp * 2 + 1;
                const uint32_t o0 = (uint32_t)(m0 * 16 * ROWB + kk * 32);
                const uint32_t o1 = (uint32_t)(m1 * 16 * ROWB + kk * 32);
                uint32_t ah0[4], al0[4], ah1[4], al1[4];
                ldsm4(ah0, aHB + o0);
                ldsm4(al0, aLB + o0);
                ldsm4(ah1, aHB + o1);
                ldsm4(al1, aLB + o1);
#pragma unroll
                for (int nt = 0; nt < 4; nt++) mma_f16(acc[m0][nt], ah0, bh[nt]);
#pragma unroll
                for (int nt = 0; nt < 4; nt++) mma_f16(acc[m1][nt], ah1, bh[nt]);
#pragma unroll
                for (int nt = 0; nt < 4; nt++) mma_f16(acc[m0][nt], al0, bh[nt]);
#pragma unroll
                for (int nt = 0; nt < 4; nt++) mma_f16(acc[m1][nt], al1, bh[nt]);
#pragma unroll
                for (int nt = 0; nt < 4; nt++) mma_f16(acc[m0][nt], ah0, bl[nt]);
#pragma unroll
                for (int nt = 0; nt < 4; nt++) mma_f16(acc[m1][nt], ah1, bl[nt]);
            }
        }
    }

    // ---- epilogue ----
    const int rbase = row0 + wr * 64 + (lane >> 2);
    const int cbase = col0 + wc * 32 + (lane & 3) * 2;
#pragma unroll
    for (int nt = 0; nt < 4; nt++) {
        const int cc = cbase + nt * 8;
        if (cc < N) {
            const float bx = bias[cc], by = bias[cc + 1];
#pragma unroll
            for (int mt = 0; mt < 4; mt++) {
                const int r = rbase + mt * 16;
                float v[4];
                v[0] = acc[mt][nt][0] + bx; v[1] = acc[mt][nt][1] + by;
                v[2] = acc[mt][nt][2] + bx; v[3] = acc[mt][nt][3] + by;
                if (RELU) {
#pragma unroll
                    for (int q = 0; q < 4; q++) v[q] = fmaxf(v[q], 0.f);
                }
                if (SPLIT_OUT) {
                    __half h0, l0, h1x, l1, h2x, l2, h3, l3;
                    split_h(v[0], h0, l0); split_h(v[1], h1x, l1);
                    split_h(v[2], h2x, l2); split_h(v[3], h3, l3);
                    *(__half2*)&Ch[(long)r * N + cc]       = __halves2half2(h0, h1x);
                    *(__half2*)&Cl[(long)r * N + cc]       = __halves2half2(l0, l1);
                    *(__half2*)&Ch[(long)(r + 8) * N + cc] = __halves2half2(h2x, h3);
                    *(__half2*)&Cl[(long)(r + 8) * N + cc] = __halves2half2(l2, l3);
                } else if (HALF_OUT) {
                    *(__half2*)&Ch[(long)r * N + cc]       = __floats2half2_rn(v[0], v[1]);
                    *(__half2*)&Ch[(long)(r + 8) * N + cc] = __floats2half2_rn(v[2], v[3]);
                } else {
                    *(float2*)&Cf[(long)r * N + cc]       = make_float2(v[0], v[1]);
                    *(float2*)&Cf[(long)(r + 8) * N + cc] = make_float2(v[2], v[3]);
                }
            }
        }
    }
}

// ---------------------------------------------------------------------------
__global__ void transpose_split_all(
    const float* __restrict__ W1, __half* __restrict__ T1h, __half* __restrict__ T1l,
    const float* __restrict__ W2, __half* __restrict__ T2h, __half* __restrict__ T2l,
    const float* __restrict__ W3, __half* __restrict__ T3h, __half* __restrict__ T3l)
{
    const float* W; __half* Th; __half* Tl; int R, C;
    if (blockIdx.z == 0)      { W = W1; Th = T1h; Tl = T1l; R = FDIM; C = HDIM; }
    else if (blockIdx.z == 1) { W = W2; Th = T2h; Tl = T2l; R = HDIM; C = HDIM; }
    else                      { W = W3; Th = T3h; Tl = T3l; R = HDIM; C = FDIM; }
    if ((int)blockIdx.x * 32 >= C || (int)blockIdx.y * 32 >= R) return;

    __shared__ float tb[32][33];
    int c = blockIdx.x * 32 + threadIdx.x;
    int r0 = blockIdx.y * 32;
    for (int j = threadIdx.y; j < 32; j += 8)
        tb[j][threadIdx.x] = W[(r0 + j) * C + c];
    __syncthreads();
    int rOut = r0 + threadIdx.x;
    int cBase = blockIdx.x * 32;
    for (int j = threadIdx.y; j < 32; j += 8) {
        float v = tb[threadIdx.x][j];
        __half h, l;
        split_h(v, h, l);
        Th[(long)(cBase + j) * R + rOut] = h;
        Tl[(long)(cBase + j) * R + rOut] = l;
    }
}

// ---------------------------------------------------------------------------
__global__ __launch_bounds__(256) void cls_kernel2(
    const float* __restrict__ ab, int* __restrict__ cls)
{
    int i = blockIdx.x * 256 + threadIdx.x;   // pair index
    if (i >= NPIX / 2) return;
    const float4* p = (const float4*)(ab + (long)i * 12);
    float4 v0 = p[0], v1 = p[1], v2 = p[2];
    float a[6] = { v0.x, v0.y, v0.z, v0.w, v1.x, v1.y };
    float b[6] = { v1.z, v1.w, v2.x, v2.y, v2.z, v2.w };
    int ba = 0, bb = 0;
    float ma = a[0], mb = b[0];
#pragma unroll
    for (int q = 1; q < 6; q++) {
        if (a[q] > ma) { ma = a[q]; ba = q; }
        if (b[q] > mb) { mb = b[q]; bb = q; }
    }
    cls[i * 2] = ba;
    cls[i * 2 + 1] = bb;
}

// ---------------------------------------------------------------------------
// Endmember partials: PLAIN-EXP sums (no max-subtraction, no serial chain).
// Valid because |logits| << 80 (MLP outputs, O(1) scale) -> no fp32 overflow.
// grid NCHUNK x 224 threads.
// ---------------------------------------------------------------------------
__global__ __launch_bounds__(224) void endmember_part3(
    const __half* __restrict__ logits, const float* __restrict__ Y,
    const int* __restrict__ cls)
{
    const int blk = blockIdx.x;
    const int t = threadIdx.x;              // feature
    const int n0 = blk * (NPIX / NCHUNK);   // 128 pixels per chunk

    __shared__ int scls[NPIX / NCHUNK];
    for (int i = t; i < NPIX / NCHUNK; i += 224) scls[i] = cls[n0 + i];
    __syncthreads();

    float s[PDIM], sy[PDIM];
#pragma unroll
    for (int p = 0; p < PDIM; p++) { s[p] = 0.f; sy[p] = 0.f; }

#pragma unroll 4
    for (int i = 0; i < NPIX / NCHUNK; i++) {
        const int c = scls[i];
        const long off = (long)(n0 + i) * FDIM + t;
        const float l = __half2float(logits[off]);
        const float y = Y[off];
        const float e = __expf(l);
        const float ey = e * y;
#pragma unroll
        for (int p = 0; p < PDIM; p++) {
            const bool msk = (c == p);
            s[p]  += msk ? e  : 0.f;
            sy[p] += msk ? ey : 0.f;
        }
    }

#pragma unroll
    for (int p = 0; p < PDIM; p++) {
        long base = (((long)blk * PDIM + p) * 2) * FDIM + t;
        g_part[base]        = s[p];
        g_part[base + FDIM] = sy[p];
    }
}

// grid PDIM blocks x 224 threads: sum per-rowblock partials
__global__ __launch_bounds__(224) void endmember_combine3(float* __restrict__ Mo) {
    const int p = blockIdx.x;
    const int f = threadIdx.x;
    float s = 0.f, sy = 0.f;
    for (int b = 0; b < NCHUNK; b++) {
        long base = (((long)b * PDIM + p) * 2) * FDIM + f;
        s  += g_part[base];
        sy += g_part[base + FDIM];
    }
    Mo[p * FDIM + f] = (s > 0.f) ? (sy / s) : 0.0f;
}

// ---------------------------------------------------------------------------
// Y_hat with float4 stores: 224 threads = 4 rows x 56 float4-groups per iter.
// ---------------------------------------------------------------------------
__global__ __launch_bounds__(224) void yhat_kernel3(
    const float* __restrict__ ab, const float* __restrict__ M,
    float* __restrict__ out)
{
    constexpr int CH = NPIX / NCHUNK;  // 128 rows per block
    __shared__ float sM[PDIM * FDIM];
    __shared__ float sab[CH * PDIM];
    const int t = threadIdx.x;
    const int n0 = blockIdx.x * CH;
    for (int i = t; i < PDIM * FDIM; i += 224) sM[i] = M[i];
    for (int i = t; i < CH * PDIM; i += 224) sab[i] = ab[(long)n0 * PDIM + i];
    __syncthreads();

    const float4* sM4 = (const float4*)sM;   // [PDIM][56]
    const int rsub = t / 56;                 // 0..3
    const int f4 = t - rsub * 56;            // 0..55

    for (int i = 0; i < CH / 4; i++) {
        const int r = i * 4 + rsub;
        float a0 = sab[r * PDIM + 0], a1 = sab[r * PDIM + 1];
        float a2 = sab[r * PDIM + 2], a3 = sab[r * PDIM + 3];
        float a4 = sab[r * PDIM + 4], a5 = sab[r * PDIM + 5];
        float4 m0 = sM4[0 * 56 + f4], m1 = sM4[1 * 56 + f4];
        float4 m2 = sM4[2 * 56 + f4], m3 = sM4[3 * 56 + f4];
        float4 m4 = sM4[4 * 56 + f4], m5 = sM4[5 * 56 + f4];
        float4 o;
        o.x = a0 * m0.x + a1 * m1.x + a2 * m2.x + a3 * m3.x + a4 * m4.x + a5 * m5.x;
        o.y = a0 * m0.y + a1 * m1.y + a2 * m2.y + a3 * m3.y + a4 * m4.y + a5 * m5.y;
        o.z = a0 * m0.z + a1 * m1.z + a2 * m2.z + a3 * m3.z + a4 * m4.z + a5 * m5.z;
        o.w = a0 * m0.w + a1 * m1.w + a2 * m2.w + a3 * m3.w + a4 * m4.w + a5 * m5.w;
        *(float4*)&out[(long)(n0 + r) * FDIM + f4 * 4] = o;
    }
}

// ---------------------------------------------------------------------------
extern "C" void kernel_launch(void* const* d_in, const int* in_sizes, int n_in,
                              void* d_out, int out_size)
{
    const float* ab = (const float*)d_in[0];
    const float* Y  = (const float*)d_in[1];
    const float* W1 = (const float*)d_in[2];
    const float* b1 = (const float*)d_in[3];
    const float* W2 = (const float*)d_in[4];
    const float* b2 = (const float*)d_in[5];
    const float* W3 = (const float*)d_in[6];
    const float* b3 = (const float*)d_in[7];
    float* out = (float*)d_out;

    __half *h1h, *h1l, *h2h, *h2l, *lg;
    __half *w1h, *w1l, *w2h, *w2l, *w3h, *w3l;
    float *M;
    int* cls;
    cudaGetSymbolAddress((void**)&h1h, g_h1h);
    cudaGetSymbolAddress((void**)&h1l, g_h1l);
    cudaGetSymbolAddress((void**)&h2h, g_h2h);
    cudaGetSymbolAddress((void**)&h2l, g_h2l);
    cudaGetSymbolAddress((void**)&w1h, g_W1Th);
    cudaGetSymbolAddress((void**)&w1l, g_W1Tl);
    cudaGetSymbolAddress((void**)&w2h, g_W2Th);
    cudaGetSymbolAddress((void**)&w2l, g_W2Tl);
    cudaGetSymbolAddress((void**)&w3h, g_W3Th);
    cudaGetSymbolAddress((void**)&w3l, g_W3Tl);
    cudaGetSymbolAddress((void**)&lg,  g_logits);
    cudaGetSymbolAddress((void**)&cls, g_cls);
    cudaGetSymbolAddress((void**)&M,   g_M);

    constexpr int SMEM = 2 * 4 * 128 * 80;           // 81920 (GEMM2/3)
    constexpr int SMEM_CONV = SMEM + 128 * 144;      // 100352 (GEMM1, fp32 staging)
    cudaFuncSetAttribute(mma_gemm_f16<HDIM, FDIM, true, true, false, true>,
                         cudaFuncAttributeMaxDynamicSharedMemorySize, SMEM_CONV);
    cudaFuncSetAttribute(mma_gemm_f16<HDIM, HDIM, true, true, false, false>,
                         cudaFuncAttributeMaxDynamicSharedMemorySize, SMEM);
    cudaFuncSetAttribute(mma_gemm_f16<FDIM, HDIM, false, false, true, false>,
                         cudaFuncAttributeMaxDynamicSharedMemorySize, SMEM);

    // prep (no Y split pass anymore)
    transpose_split_all<<<dim3(8, 8, 3), dim3(32, 8)>>>(
        W1, w1h, w1l, W2, w2h, w2l, W3, w3h, w3l);
    cls_kernel2<<<(NPIX / 2 + 255) / 256, 256>>>(ab, cls);

    // GEMM chain; GEMM1 converts fp32 Y in-kernel; GEMM3 writes fp16 logits
    mma_gemm_f16<HDIM, FDIM, true, true, false, true><<<dim3(2, NPIX / 128), 256, SMEM_CONV>>>(
        nullptr, nullptr, w1h, w1l, b1, nullptr, h1h, h1l, Y);
    mma_gemm_f16<HDIM, HDIM, true, true, false, false><<<dim3(2, NPIX / 128), 256, SMEM>>>(
        h1h, h1l, w2h, w2l, b2, nullptr, h2h, h2l, nullptr);
    mma_gemm_f16<FDIM, HDIM, false, false, true, false><<<dim3(2, NPIX / 128), 256, SMEM>>>(
        h2h, h2l, w3h, w3l, b3, nullptr, lg, nullptr, nullptr);

    // masked per-class plain-exp sums -> endmembers
    endmember_part3<<<NCHUNK, 224>>>(lg, Y, cls);
    endmember_combine3<<<PDIM, 224>>>(M);

    // reconstruction
    yhat_kernel3<<<NCHUNK, 224>>>(ab, M, out);
}

// round 17
// speedup vs baseline: 1.5436x; 1.1803x over previous
#include <cuda_runtime.h>
#include <cuda_fp16.h>
#include <cstdint>
#include <float.h>

#define NPIX 65536
#define FDIM 224
#define PDIM 6
#define HDIM 256
#define NCHUNK 512          // pixel row-blocks (128 px each)

// ------------------------- static device scratch ---------------------------
__device__ __half g_h1h[NPIX * HDIM];
__device__ __half g_h1l[NPIX * HDIM];
__device__ __half g_h2h[NPIX * HDIM];
__device__ __half g_logits[NPIX * FDIM];   // fp16 logits (hi)
__device__ int    g_cls[NPIX];
__device__ float  g_M[PDIM * FDIM];
__device__ __half g_W1Th[HDIM * FDIM];
__device__ __half g_W1Tl[HDIM * FDIM];
__device__ __half g_W2Th[HDIM * HDIM];
__device__ __half g_W2Tl[HDIM * HDIM];
__device__ __half g_W3Th[FDIM * HDIM];
__device__ __half g_W3Tl[FDIM * HDIM];
// per-rowblock partials: [rowblk][class][{s,sy}][FDIM]  (plain-exp sums)
__device__ float  g_part[NCHUNK * PDIM * 2 * FDIM];

struct half2x2 { __half2 a, b; };   // 8-byte vector for STS.64

// ------------------------------ PTX helpers --------------------------------
__device__ __forceinline__ uint32_t smem_u32(const void* p) {
    uint32_t a;
    asm("{ .reg .u64 t; cvta.to.shared.u64 t, %1; cvt.u32.u64 %0, t; }"
        : "=r"(a) : "l"(p));
    return a;
}
__device__ __forceinline__ void cpa16(uint32_t dst, const void* src, uint32_t sz) {
    asm volatile("cp.async.cg.shared.global [%0], [%1], 16, %2;"
                 :: "r"(dst), "l"(src), "r"(sz) : "memory");
}
__device__ __forceinline__ void cpa_commit() {
    asm volatile("cp.async.commit_group;" ::: "memory");
}
template <int n> __device__ __forceinline__ void cpa_wait() {
    asm volatile("cp.async.wait_group %0;" :: "n"(n) : "memory");
}
__device__ __forceinline__ void ldsm4(uint32_t* r, uint32_t addr) {
    asm volatile("ldmatrix.sync.aligned.m8n8.x4.shared.b16 {%0,%1,%2,%3}, [%4];"
                 : "=r"(r[0]), "=r"(r[1]), "=r"(r[2]), "=r"(r[3]) : "r"(addr));
}
__device__ __forceinline__ void mma_f16(float* d, const uint32_t* a, const uint32_t* b) {
    asm volatile(
        "mma.sync.aligned.m16n8k16.row.col.f32.f16.f16.f32 "
        "{%0,%1,%2,%3}, {%4,%5,%6,%7}, {%8,%9}, {%0,%1,%2,%3};"
        : "+f"(d[0]), "+f"(d[1]), "+f"(d[2]), "+f"(d[3])
        : "r"(a[0]), "r"(a[1]), "r"(a[2]), "r"(a[3]), "r"(b[0]), "r"(b[1]));
}
__device__ __forceinline__ void split_h(float v, __half& hi, __half& lo) {
    hi = __float2half_rn(v);
    lo = __float2half_rn(v - __half2float(hi));
}

// ---------------------------------------------------------------------------
// fp16 mma.sync GEMM: C = act(A @ BT^T + bias).
// Block 128x128, 8 warps (2x4), warp tile 64x32, K chunks of 32, 2-stage
// cp.async, paired-mt MMA schedule.
// TERMS=3: fp16x3 error-compensated (hi/lo operands, fp32-accurate).
// TERMS=1: plain fp16 (hi operands only) -- used for the logits GEMM whose
//          output is fp16-rounded anyway (error ~2e-4 ~ store rounding).
// SPLIT_OUT: hi/lo fp16 pair outputs. HALF_OUT: single fp16 output.
// CONV_A: A supplied as fp32; staged + converted in-kernel to hi/lo layout.
// ---------------------------------------------------------------------------
template <int N, int K, bool RELU, bool SPLIT_OUT, bool HALF_OUT, bool CONV_A, int TERMS>
__global__ __launch_bounds__(256, 2) void mma_gemm_f16(
    const __half* __restrict__ Ah, const __half* __restrict__ Al,
    const __half* __restrict__ Bh, const __half* __restrict__ Bl,
    const float* __restrict__ bias,
    float* __restrict__ Cf, __half* __restrict__ Ch, __half* __restrict__ Cl,
    const float* __restrict__ Af32)
{
    constexpr int NC = K / 32;
    constexpr int ROWB = 80;               // fp16 bytes/row: 64B data + 16B pad
    constexpr int COMPB = 128 * ROWB;      // 10240 per component tile
    constexpr int STAGEB = 4 * COMPB;      // 40960: [Ah][Al][Bh][Bl]
    constexpr int A32OFF = 2 * STAGEB;     // 81920: fp32 A staging (CONV_A)
    constexpr int A32ROWB = 144;           // 128B data + 16B pad

    extern __shared__ char sh[];
    const uint32_t sb = smem_u32(sh);

    const int t = threadIdx.x;
    const int lane = t & 31, wid = t >> 5;
    const int wr = wid >> 2;               // 0..1
    const int wc = wid & 3;                // 0..3
    const int row0 = blockIdx.y * 128;
    const int col0 = blockIdx.x * 128;

    float acc[4][4][4];
#pragma unroll
    for (int i = 0; i < 4; i++)
#pragma unroll
        for (int j = 0; j < 4; j++)
#pragma unroll
            for (int k = 0; k < 4; k++) acc[i][j][k] = 0.0f;

    // ---- fp16 A cp.async mapping (non-CONV_A) ----
    const int cr = t >> 2;
    const int g  = t & 3;
    const uint32_t dOff1 = (uint32_t)(cr * ROWB + g * 16);
    const uint32_t dOff2 = dOff1 + (uint32_t)(64 * ROWB);
    const __half* Ah0 = CONV_A ? nullptr : (Ah + (long)(row0 + cr) * K + g * 8);
    const __half* Al0 = (CONV_A || TERMS == 1) ? nullptr
                                               : (Al + (long)(row0 + cr) * K + g * 8);

    // ---- fp32 A staging mapping (CONV_A): 4 shots of 16B per thread ----
    const int c_row = t >> 3;              // base rows for shots: c_row + 32*j
    const int c_grp = t & 7;

    // ---- B cp.async mapping ----
    int bn1 = col0 + cr, bn2 = col0 + cr + 64;
    const uint32_t bs1 = (bn1 < N) ? 16u : 0u;
    const uint32_t bs2 = (bn2 < N) ? 16u : 0u;
    if (bn1 >= N) bn1 = N - 1;
    if (bn2 >= N) bn2 = N - 1;
    const __half* Bh1 = Bh + (long)bn1 * K + g * 8;
    const __half* Bh2 = Bh + (long)bn2 * K + g * 8;
    const __half* Bl1 = (TERMS == 1) ? nullptr : (Bl + (long)bn1 * K + g * 8);
    const __half* Bl2 = (TERMS == 1) ? nullptr : (Bl + (long)bn2 * K + g * 8);

    const uint32_t aLm = (uint32_t)((wr * 64 + (lane & 15)) * ROWB + (lane >> 4) * 16);
    const uint32_t bLm = (uint32_t)((wc * 32 + (lane & 7) + ((lane >> 4) << 3)) * ROWB
                                    + ((lane >> 3) & 1) * 16);

    auto load_B = [&](int stage, int k0) {
        const uint32_t st = sb + (uint32_t)(stage * STAGEB);
        cpa16(st + 2 * COMPB + dOff1,     Bh1 + k0,           bs1);
        cpa16(st + 2 * COMPB + dOff2,     Bh2 + k0,           bs2);
        if (TERMS == 3) {
            cpa16(st + 3 * COMPB + dOff1, Bl1 + k0,           bs1);
            cpa16(st + 3 * COMPB + dOff2, Bl2 + k0,           bs2);
        }
    };
    auto load_A16 = [&](int stage, int k0) {
        const uint32_t st = sb + (uint32_t)(stage * STAGEB);
        cpa16(st + dOff1,             Ah0 + k0,           16u);
        cpa16(st + dOff2,             Ah0 + k0 + 64L * K, 16u);
        if (TERMS == 3) {
            cpa16(st + COMPB + dOff1, Al0 + k0,           16u);
            cpa16(st + COMPB + dOff2, Al0 + k0 + 64L * K, 16u);
        }
    };
    auto load_A32 = [&](int k0) {
#pragma unroll
        for (int j = 0; j < 4; j++) {
            const int row = c_row + 32 * j;
            cpa16(sb + (uint32_t)(A32OFF + row * A32ROWB + c_grp * 16),
                  Af32 + (long)(row0 + row) * K + k0 + c_grp * 4, 16u);
        }
    };

    // prologue: chunk 0
    if (CONV_A) load_A32(0); else load_A16(0, 0);
    load_B(0, 0);
    cpa_commit();

    for (int c = 0; c < NC; c++) {
        const int buf = c & 1;
        cpa_wait<0>();                     // chunk c resident
        __syncthreads();                   // fences buf^1 fp16 reuse + A32 reads

        if (CONV_A) {
            // convert A32(c) -> fp16 Ah/Al of stage(buf)
            char* abase = sh + buf * STAGEB;
#pragma unroll
            for (int j = 0; j < 4; j++) {
                const int row = c_row + 32 * j;
                const float4 v = *(const float4*)(sh + A32OFF + row * A32ROWB + c_grp * 16);
                __half h0, l0, h1, l1, h2, l2, h3, l3;
                split_h(v.x, h0, l0); split_h(v.y, h1, l1);
                split_h(v.z, h2, l2); split_h(v.w, h3, l3);
                half2x2 hv, lv;
                hv.a = __halves2half2(h0, h1); hv.b = __halves2half2(h2, h3);
                lv.a = __halves2half2(l0, l1); lv.b = __halves2half2(l2, l3);
                const int doff = row * ROWB + c_grp * 8;
                *(half2x2*)(abase + doff)         = hv;
                *(half2x2*)(abase + COMPB + doff) = lv;
            }
            __syncthreads();               // conversion visible; A32 free
            if (c + 1 < NC) {
                load_A32((c + 1) * 32);
                load_B(buf ^ 1, (c + 1) * 32);
                cpa_commit();
            }
        } else {
            if (c + 1 < NC) {
                load_A16(buf ^ 1, (c + 1) * 32);
                load_B(buf ^ 1, (c + 1) * 32);
                cpa_commit();
            }
        }

        const uint32_t st = sb + (uint32_t)(buf * STAGEB);
        const uint32_t aHB = st + aLm;
        const uint32_t aLB = st + COMPB + aLm;
        const uint32_t bHB = st + 2 * COMPB + bLm;
        const uint32_t bLB = st + 3 * COMPB + bLm;

#pragma unroll
        for (int kk = 0; kk < 2; kk++) {
            uint32_t bh[4][2], bl[4][2];
#pragma unroll
            for (int pr = 0; pr < 2; pr++) {
                const uint32_t o = (uint32_t)(pr * 16 * ROWB + kk * 32);
                uint32_t r4[4];
                ldsm4(r4, bHB + o);
                bh[pr * 2][0] = r4[0]; bh[pr * 2][1] = r4[1];
                bh[pr * 2 + 1][0] = r4[2]; bh[pr * 2 + 1][1] = r4[3];
                if (TERMS == 3) {
                    ldsm4(r4, bLB + o);
                    bl[pr * 2][0] = r4[0]; bl[pr * 2][1] = r4[1];
                    bl[pr * 2 + 1][0] = r4[2]; bl[pr * 2 + 1][1] = r4[3];
                }
            }
#pragma unroll
            for (int mp = 0; mp < 2; mp++) {
                const int m0 = mp * 2, m1 = mp * 2 + 1;
                const uint32_t o0 = (uint32_t)(m0 * 16 * ROWB + kk * 32);
                const uint32_t o1 = (uint32_t)(m1 * 16 * ROWB + kk * 32);
                uint32_t ah0[4], al0[4], ah1[4], al1[4];
                ldsm4(ah0, aHB + o0);
                if (TERMS == 3) ldsm4(al0, aLB + o0);
                ldsm4(ah1, aHB + o1);
                if (TERMS == 3) ldsm4(al1, aLB + o1);
#pragma unroll
                for (int nt = 0; nt < 4; nt++) mma_f16(acc[m0][nt], ah0, bh[nt]);
#pragma unroll
                for (int nt = 0; nt < 4; nt++) mma_f16(acc[m1][nt], ah1, bh[nt]);
                if (TERMS == 3) {
#pragma unroll
                    for (int nt = 0; nt < 4; nt++) mma_f16(acc[m0][nt], al0, bh[nt]);
#pragma unroll
                    for (int nt = 0; nt < 4; nt++) mma_f16(acc[m1][nt], al1, bh[nt]);
#pragma unroll
                    for (int nt = 0; nt < 4; nt++) mma_f16(acc[m0][nt], ah0, bl[nt]);
#pragma unroll
                    for (int nt = 0; nt < 4; nt++) mma_f16(acc[m1][nt], ah1, bl[nt]);
                }
            }
        }
    }

    // ---- epilogue ----
    const int rbase = row0 + wr * 64 + (lane >> 2);
    const int cbase = col0 + wc * 32 + (lane & 3) * 2;
#pragma unroll
    for (int nt = 0; nt < 4; nt++) {
        const int cc = cbase + nt * 8;
        if (cc < N) {
            const float bx = bias[cc], by = bias[cc + 1];
#pragma unroll
            for (int mt = 0; mt < 4; mt++) {
                const int r = rbase + mt * 16;
                float v[4];
                v[0] = acc[mt][nt][0] + bx; v[1] = acc[mt][nt][1] + by;
                v[2] = acc[mt][nt][2] + bx; v[3] = acc[mt][nt][3] + by;
                if (RELU) {
#pragma unroll
                    for (int q = 0; q < 4; q++) v[q] = fmaxf(v[q], 0.f);
                }
                if (SPLIT_OUT) {
                    __half h0, l0, h1x, l1, h2x, l2, h3, l3;
                    split_h(v[0], h0, l0); split_h(v[1], h1x, l1);
                    split_h(v[2], h2x, l2); split_h(v[3], h3, l3);
                    *(__half2*)&Ch[(long)r * N + cc]       = __halves2half2(h0, h1x);
                    *(__half2*)&Cl[(long)r * N + cc]       = __halves2half2(l0, l1);
                    *(__half2*)&Ch[(long)(r + 8) * N + cc] = __halves2half2(h2x, h3);
                    *(__half2*)&Cl[(long)(r + 8) * N + cc] = __halves2half2(l2, l3);
                } else if (HALF_OUT) {
                    *(__half2*)&Ch[(long)r * N + cc]       = __floats2half2_rn(v[0], v[1]);
                    *(__half2*)&Ch[(long)(r + 8) * N + cc] = __floats2half2_rn(v[2], v[3]);
                } else {
                    *(float2*)&Cf[(long)r * N + cc]       = make_float2(v[0], v[1]);
                    *(float2*)&Cf[(long)(r + 8) * N + cc] = make_float2(v[2], v[3]);
                }
            }
        }
    }
}

// ---------------------------------------------------------------------------
__global__ void transpose_split_all(
    const float* __restrict__ W1, __half* __restrict__ T1h, __half* __restrict__ T1l,
    const float* __restrict__ W2, __half* __restrict__ T2h, __half* __restrict__ T2l,
    const float* __restrict__ W3, __half* __restrict__ T3h, __half* __restrict__ T3l)
{
    const float* W; __half* Th; __half* Tl; int R, C;
    if (blockIdx.z == 0)      { W = W1; Th = T1h; Tl = T1l; R = FDIM; C = HDIM; }
    else if (blockIdx.z == 1) { W = W2; Th = T2h; Tl = T2l; R = HDIM; C = HDIM; }
    else                      { W = W3; Th = T3h; Tl = T3l; R = HDIM; C = FDIM; }
    if ((int)blockIdx.x * 32 >= C || (int)blockIdx.y * 32 >= R) return;

    __shared__ float tb[32][33];
    int c = blockIdx.x * 32 + threadIdx.x;
    int r0 = blockIdx.y * 32;
    for (int j = threadIdx.y; j < 32; j += 8)
        tb[j][threadIdx.x] = W[(r0 + j) * C + c];
    __syncthreads();
    int rOut = r0 + threadIdx.x;
    int cBase = blockIdx.x * 32;
    for (int j = threadIdx.y; j < 32; j += 8) {
        float v = tb[threadIdx.x][j];
        __half h, l;
        split_h(v, h, l);
        Th[(long)(cBase + j) * R + rOut] = h;
        Tl[(long)(cBase + j) * R + rOut] = l;
    }
}

// ---------------------------------------------------------------------------
__global__ __launch_bounds__(256) void cls_kernel2(
    const float* __restrict__ ab, int* __restrict__ cls)
{
    int i = blockIdx.x * 256 + threadIdx.x;   // pair index
    if (i >= NPIX / 2) return;
    const float4* p = (const float4*)(ab + (long)i * 12);
    float4 v0 = p[0], v1 = p[1], v2 = p[2];
    float a[6] = { v0.x, v0.y, v0.z, v0.w, v1.x, v1.y };
    float b[6] = { v1.z, v1.w, v2.x, v2.y, v2.z, v2.w };
    int ba = 0, bb = 0;
    float ma = a[0], mb = b[0];
#pragma unroll
    for (int q = 1; q < 6; q++) {
        if (a[q] > ma) { ma = a[q]; ba = q; }
        if (b[q] > mb) { mb = b[q]; bb = q; }
    }
    cls[i * 2] = ba;
    cls[i * 2 + 1] = bb;
}

// ---------------------------------------------------------------------------
// Endmember partials: PLAIN-EXP sums (no max-subtraction, no serial chain).
// grid NCHUNK x 224 threads.
// ---------------------------------------------------------------------------
__global__ __launch_bounds__(224) void endmember_part3(
    const __half* __restrict__ logits, const float* __restrict__ Y,
    const int* __restrict__ cls)
{
    const int blk = blockIdx.x;
    const int t = threadIdx.x;              // feature
    const int n0 = blk * (NPIX / NCHUNK);   // 128 pixels per chunk

    __shared__ int scls[NPIX / NCHUNK];
    for (int i = t; i < NPIX / NCHUNK; i += 224) scls[i] = cls[n0 + i];
    __syncthreads();

    float s[PDIM], sy[PDIM];
#pragma unroll
    for (int p = 0; p < PDIM; p++) { s[p] = 0.f; sy[p] = 0.f; }

#pragma unroll 4
    for (int i = 0; i < NPIX / NCHUNK; i++) {
        const int c = scls[i];
        const long off = (long)(n0 + i) * FDIM + t;
        const float l = __half2float(logits[off]);
        const float y = Y[off];
        const float e = __expf(l);
        const float ey = e * y;
#pragma unroll
        for (int p = 0; p < PDIM; p++) {
            const bool msk = (c == p);
            s[p]  += msk ? e  : 0.f;
            sy[p] += msk ? ey : 0.f;
        }
    }

#pragma unroll
    for (int p = 0; p < PDIM; p++) {
        long base = (((long)blk * PDIM + p) * 2) * FDIM + t;
        g_part[base]        = s[p];
        g_part[base + FDIM] = sy[p];
    }
}

// grid PDIM blocks x 224 threads: sum per-rowblock partials
__global__ __launch_bounds__(224) void endmember_combine3(float* __restrict__ Mo) {
    const int p = blockIdx.x;
    const int f = threadIdx.x;
    float s = 0.f, sy = 0.f;
    for (int b = 0; b < NCHUNK; b++) {
        long base = (((long)b * PDIM + p) * 2) * FDIM + f;
        s  += g_part[base];
        sy += g_part[base + FDIM];
    }
    Mo[p * FDIM + f] = (s > 0.f) ? (sy / s) : 0.0f;
}

// ---------------------------------------------------------------------------
// Y_hat with float4 stores: 224 threads = 4 rows x 56 float4-groups per iter.
// ---------------------------------------------------------------------------
__global__ __launch_bounds__(224) void yhat_kernel3(
    const float* __restrict__ ab, const float* __restrict__ M,
    float* __restrict__ out)
{
    constexpr int CH = NPIX / NCHUNK;  // 128 rows per block
    __shared__ float sM[PDIM * FDIM];
    __shared__ float sab[CH * PDIM];
    const int t = threadIdx.x;
    const int n0 = blockIdx.x * CH;
    for (int i = t; i < PDIM * FDIM; i += 224) sM[i] = M[i];
    for (int i = t; i < CH * PDIM; i += 224) sab[i] = ab[(long)n0 * PDIM + i];
    __syncthreads();

    const float4* sM4 = (const float4*)sM;   // [PDIM][56]
    const int rsub = t / 56;                 // 0..3
    const int f4 = t - rsub * 56;            // 0..55

    for (int i = 0; i < CH / 4; i++) {
        const int r = i * 4 + rsub;
        float a0 = sab[r * PDIM + 0], a1 = sab[r * PDIM + 1];
        float a2 = sab[r * PDIM + 2], a3 = sab[r * PDIM + 3];
        float a4 = sab[r * PDIM + 4], a5 = sab[r * PDIM + 5];
        float4 m0 = sM4[0 * 56 + f4], m1 = sM4[1 * 56 + f4];
        float4 m2 = sM4[2 * 56 + f4], m3 = sM4[3 * 56 + f4];
        float4 m4 = sM4[4 * 56 + f4], m5 = sM4[5 * 56 + f4];
        float4 o;
        o.x = a0 * m0.x + a1 * m1.x + a2 * m2.x + a3 * m3.x + a4 * m4.x + a5 * m5.x;
        o.y = a0 * m0.y + a1 * m1.y + a2 * m2.y + a3 * m3.y + a4 * m4.y + a5 * m5.y;
        o.z = a0 * m0.z + a1 * m1.z + a2 * m2.z + a3 * m3.z + a4 * m4.z + a5 * m5.z;
        o.w = a0 * m0.w + a1 * m1.w + a2 * m2.w + a3 * m3.w + a4 * m4.w + a5 * m5.w;
        *(float4*)&out[(long)(n0 + r) * FDIM + f4 * 4] = o;
    }
}

// ---------------------------------------------------------------------------
extern "C" void kernel_launch(void* const* d_in, const int* in_sizes, int n_in,
                              void* d_out, int out_size)
{
    const float* ab = (const float*)d_in[0];
    const float* Y  = (const float*)d_in[1];
    const float* W1 = (const float*)d_in[2];
    const float* b1 = (const float*)d_in[3];
    const float* W2 = (const float*)d_in[4];
    const float* b2 = (const float*)d_in[5];
    const float* W3 = (const float*)d_in[6];
    const float* b3 = (const float*)d_in[7];
    float* out = (float*)d_out;

    __half *h1h, *h1l, *h2h, *lg;
    __half *w1h, *w1l, *w2h, *w2l, *w3h, *w3l;
    float *M;
    int* cls;
    cudaGetSymbolAddress((void**)&h1h, g_h1h);
    cudaGetSymbolAddress((void**)&h1l, g_h1l);
    cudaGetSymbolAddress((void**)&h2h, g_h2h);
    cudaGetSymbolAddress((void**)&w1h, g_W1Th);
    cudaGetSymbolAddress((void**)&w1l, g_W1Tl);
    cudaGetSymbolAddress((void**)&w2h, g_W2Th);
    cudaGetSymbolAddress((void**)&w2l, g_W2Tl);
    cudaGetSymbolAddress((void**)&w3h, g_W3Th);
    cudaGetSymbolAddress((void**)&w3l, g_W3Tl);
    cudaGetSymbolAddress((void**)&lg,  g_logits);
    cudaGetSymbolAddress((void**)&cls, g_cls);
    cudaGetSymbolAddress((void**)&M,   g_M);

    constexpr int SMEM = 2 * 4 * 128 * 80;           // 81920 (GEMM2/3)
    constexpr int SMEM_CONV = SMEM + 128 * 144;      // 100352 (GEMM1, fp32 staging)
    cudaFuncSetAttribute(mma_gemm_f16<HDIM, FDIM, true, true, false, true, 3>,
                         cudaFuncAttributeMaxDynamicSharedMemorySize, SMEM_CONV);
    cudaFuncSetAttribute(mma_gemm_f16<HDIM, HDIM, true, false, true, false, 3>,
                         cudaFuncAttributeMaxDynamicSharedMemorySize, SMEM);
    cudaFuncSetAttribute(mma_gemm_f16<FDIM, HDIM, false, false, true, false, 1>,
                         cudaFuncAttributeMaxDynamicSharedMemorySize, SMEM);

    // prep
    transpose_split_all<<<dim3(8, 8, 3), dim3(32, 8)>>>(
        W1, w1h, w1l, W2, w2h, w2l, W3, w3h, w3l);
    cls_kernel2<<<(NPIX / 2 + 255) / 256, 256>>>(ab, cls);

    // GEMM chain:
    //  GEMM1: fp32 Y converted in-kernel, fp16x3, hi/lo h1 out
    //  GEMM2: fp16x3, fp16(hi) h2 out (GEMM3 is 1-term, lo not needed)
    //  GEMM3: pure fp16 (1 term), fp16 logits out
    mma_gemm_f16<HDIM, FDIM, true, true, false, true, 3><<<dim3(2, NPIX / 128), 256, SMEM_CONV>>>(
        nullptr, nullptr, w1h, w1l, b1, nullptr, h1h, h1l, Y);
    mma_gemm_f16<HDIM, HDIM, true, false, true, false, 3><<<dim3(2, NPIX / 128), 256, SMEM>>>(
        h1h, h1l, w2h, w2l, b2, nullptr, h2h, nullptr, nullptr);
    mma_gemm_f16<FDIM, HDIM, false, false, true, false, 1><<<dim3(2, NPIX / 128), 256, SMEM>>>(
        h2h, nullptr, w3h, nullptr, b3, nullptr, lg, nullptr, nullptr);

    // masked per-class plain-exp sums -> endmembers
    endmember_part3<<<NCHUNK, 224>>>(lg, Y, cls);
    endmember_combine3<<<PDIM, 224>>>(M);

    // reconstruction
    yhat_kernel3<<<NCHUNK, 224>>>(ab, M, out);
}